// round 6
// baseline (speedup 1.0000x reference)
#include <cuda_runtime.h>
#include <cstdint>

#define TSEQ 2048
#define BB   2
#define EMB  1024
#define NH   16
#define HD   64
#define E3   3072
#define MROWS 4096   // T*B
#define SCALING 0.125f

// Scratch (no cudaMalloc allowed) ------------------------------------------
__device__ float g_proj[(size_t)MROWS * E3];   // [T*B, 3E] : q | k | v
__device__ float g_attn[(size_t)MROWS * EMB];  // [T*B, E]  : attention output

// ---------------------------------------------------------------------------
// SGEMM:  C[M,N] = A[M,K] * B[N,K]^T + bias[N]
// 128x128 block tile, BK=16, 256 threads, 8x8 per thread.
// ---------------------------------------------------------------------------
__global__ void __launch_bounds__(256)
sgemm_nt_bias(const float* __restrict__ A, const float* __restrict__ B,
              const float* __restrict__ bias, float* __restrict__ C,
              int M, int N, int K)
{
    __shared__ float As[16][132];   // [k][m], padded
    __shared__ float Bs[16][132];   // [k][n], padded

    const int tid = threadIdx.x;
    const int tx = tid & 15, ty = tid >> 4;
    const int m0 = blockIdx.y * 128;
    const int n0 = blockIdx.x * 128;

    const float* Ab = A + (size_t)m0 * K;
    const float* Bb = B + (size_t)n0 * K;

    float acc[8][8];
#pragma unroll
    for (int i = 0; i < 8; i++)
#pragma unroll
        for (int j = 0; j < 8; j++) acc[i][j] = 0.f;

    const int r0 = tid >> 2;          // 0..63
    const int c0 = (tid & 3) * 4;     // 0,4,8,12 within the 16-wide K slice

    for (int kt = 0; kt < K; kt += 16) {
#pragma unroll
        for (int i = 0; i < 2; i++) {
            int r = r0 + i * 64;
            float4 va = *(const float4*)(Ab + (size_t)r * K + kt + c0);
            As[c0 + 0][r] = va.x; As[c0 + 1][r] = va.y;
            As[c0 + 2][r] = va.z; As[c0 + 3][r] = va.w;
            float4 vb = *(const float4*)(Bb + (size_t)r * K + kt + c0);
            Bs[c0 + 0][r] = vb.x; Bs[c0 + 1][r] = vb.y;
            Bs[c0 + 2][r] = vb.z; Bs[c0 + 3][r] = vb.w;
        }
        __syncthreads();
#pragma unroll
        for (int k = 0; k < 16; k++) {
            float a[8], b[8];
            *(float4*)(a)     = *(const float4*)&As[k][ty * 8];
            *(float4*)(a + 4) = *(const float4*)&As[k][ty * 8 + 4];
            *(float4*)(b)     = *(const float4*)&Bs[k][tx * 8];
            *(float4*)(b + 4) = *(const float4*)&Bs[k][tx * 8 + 4];
#pragma unroll
            for (int i = 0; i < 8; i++)
#pragma unroll
                for (int j = 0; j < 8; j++)
                    acc[i][j] += a[i] * b[j];
        }
        __syncthreads();
    }

    // epilogue: add bias, write
    float bl[8];
#pragma unroll
    for (int j = 0; j < 8; j++) bl[j] = bias[n0 + tx * 8 + j];
#pragma unroll
    for (int i = 0; i < 8; i++) {
        int row = m0 + ty * 8 + i;
        float* Cr = C + (size_t)row * N + n0 + tx * 8;
        float4 o0, o1;
        o0.x = acc[i][0] + bl[0]; o0.y = acc[i][1] + bl[1];
        o0.z = acc[i][2] + bl[2]; o0.w = acc[i][3] + bl[3];
        o1.x = acc[i][4] + bl[4]; o1.y = acc[i][5] + bl[5];
        o1.z = acc[i][6] + bl[6]; o1.w = acc[i][7] + bl[7];
        *(float4*)(Cr)     = o0;
        *(float4*)(Cr + 4) = o1;
    }
}

// ---------------------------------------------------------------------------
// Flash attention, fp32. One block = 64 queries of one (b,h).
// 256 threads as 16x16; thread owns 4x4 of each 64x64 tile.
// Mask is read as uint32 words: NONZERO bits == padded key. This is correct
// whether the harness widened the bool to int32 (1) or float32 (1.0f).
// ---------------------------------------------------------------------------
__device__ __forceinline__ float rmax16(float v) {
    v = fmaxf(v, __shfl_xor_sync(0xffffffffu, v, 8));
    v = fmaxf(v, __shfl_xor_sync(0xffffffffu, v, 4));
    v = fmaxf(v, __shfl_xor_sync(0xffffffffu, v, 2));
    v = fmaxf(v, __shfl_xor_sync(0xffffffffu, v, 1));
    return v;
}
__device__ __forceinline__ float rsum16(float v) {
    v += __shfl_xor_sync(0xffffffffu, v, 8);
    v += __shfl_xor_sync(0xffffffffu, v, 4);
    v += __shfl_xor_sync(0xffffffffu, v, 2);
    v += __shfl_xor_sync(0xffffffffu, v, 1);
    return v;
}

__global__ void __launch_bounds__(256)
attn_kernel(const float* __restrict__ proj, const uint32_t* __restrict__ mask,
            float* __restrict__ out)
{
    __shared__ float Qs[64][64];   // [d][r], pre-scaled by SCALING
    __shared__ float KP[64][64];   // K as [d][s]; reused as P[r][s]
    __shared__ float Vs[64][64];   // [s][d]

    const int tid = threadIdx.x;
    const int tx = tid & 15, ty = tid >> 4;
    const int qt = blockIdx.x, h = blockIdx.y, b = blockIdx.z;
    const int q0 = qt * 64;

    const int rl = tid >> 2;        // local row 0..63
    const int jj = tid & 3;         // which float4 group

    // ---- load Q (transposed, scaled) ----
    {
        size_t base = ((size_t)(q0 + rl) * BB + b) * E3 + h * HD;
#pragma unroll
        for (int p = 0; p < 4; p++) {
            int d0 = (jj + p * 4) * 4;
            float4 v = *(const float4*)(proj + base + d0);
            Qs[d0 + 0][rl] = v.x * SCALING;
            Qs[d0 + 1][rl] = v.y * SCALING;
            Qs[d0 + 2][rl] = v.z * SCALING;
            Qs[d0 + 3][rl] = v.w * SCALING;
        }
    }

    float m[4], l[4], acc[4][4];
#pragma unroll
    for (int i = 0; i < 4; i++) {
        m[i] = -1e30f; l[i] = 0.f;
#pragma unroll
        for (int j = 0; j < 4; j++) acc[i][j] = 0.f;
    }

    const uint32_t* mrow = mask + (size_t)b * TSEQ;   // one word per key pos

    for (int kt = 0; kt < TSEQ / 64; kt++) {
        __syncthreads();            // previous iteration readers done
        const int s0 = kt * 64;

        // ---- load K (transposed) and V tiles ----
        size_t kbase = ((size_t)(s0 + rl) * BB + b) * E3 + EMB + h * HD;
        size_t vbase = kbase + EMB;
#pragma unroll
        for (int p = 0; p < 4; p++) {
            int d0 = (jj + p * 4) * 4;
            float4 kv = *(const float4*)(proj + kbase + d0);
            KP[d0 + 0][rl] = kv.x; KP[d0 + 1][rl] = kv.y;
            KP[d0 + 2][rl] = kv.z; KP[d0 + 3][rl] = kv.w;
            float4 vv = *(const float4*)(proj + vbase + d0);
            *(float4*)&Vs[rl][d0] = vv;
        }
        // barrier doubles as tile-validity count (mask is monotone: pad suffix)
        int nvalid = __syncthreads_count((int)(mrow[s0 + (tid & 63)] == 0u));
        if (nvalid == 0) break;

        // ---- S = Q K^T  (4x4 per thread) ----
        float s[4][4];
#pragma unroll
        for (int i = 0; i < 4; i++)
#pragma unroll
            for (int j = 0; j < 4; j++) s[i][j] = 0.f;
#pragma unroll
        for (int d = 0; d < 64; d++) {
            float4 aq = *(const float4*)&Qs[d][ty * 4];
            float4 bk = *(const float4*)&KP[d][tx * 4];
            float av[4] = {aq.x, aq.y, aq.z, aq.w};
            float bv[4] = {bk.x, bk.y, bk.z, bk.w};
#pragma unroll
            for (int i = 0; i < 4; i++)
#pragma unroll
                for (int j = 0; j < 4; j++)
                    s[i][j] += av[i] * bv[j];
        }

        // ---- key padding mask (nonzero word == pad) ----
        float madd[4];
#pragma unroll
        for (int j = 0; j < 4; j++)
            madd[j] = (mrow[s0 + tx * 4 + j] != 0u) ? -1e30f : 0.f;
#pragma unroll
        for (int i = 0; i < 4; i++)
#pragma unroll
            for (int j = 0; j < 4; j++)
                s[i][j] += madd[j];

        // ---- online softmax ----
        float corr[4];
#pragma unroll
        for (int i = 0; i < 4; i++) {
            float tm = fmaxf(fmaxf(s[i][0], s[i][1]), fmaxf(s[i][2], s[i][3]));
            tm = rmax16(tm);
            float mn = fmaxf(m[i], tm);
            corr[i] = __expf(m[i] - mn);
            m[i] = mn;
            float rs = 0.f;
#pragma unroll
            for (int j = 0; j < 4; j++) {
                float p = __expf(s[i][j] - mn);
                s[i][j] = p;
                rs += p;
            }
            rs = rsum16(rs);
            l[i] = l[i] * corr[i] + rs;
#pragma unroll
            for (int j = 0; j < 4; j++) acc[i][j] *= corr[i];
        }

        __syncthreads();            // done reading KP as K
        // ---- store P into KP as [r][s] ----
#pragma unroll
        for (int i = 0; i < 4; i++) {
            float4 pv = make_float4(s[i][0], s[i][1], s[i][2], s[i][3]);
            *(float4*)&KP[ty * 4 + i][tx * 4] = pv;
        }
        __syncthreads();

        // ---- O += P V ----
#pragma unroll
        for (int s4 = 0; s4 < 16; s4++) {
            float pr[4][4];
#pragma unroll
            for (int i = 0; i < 4; i++) {
                float4 t = *(const float4*)&KP[ty * 4 + i][s4 * 4];
                pr[i][0] = t.x; pr[i][1] = t.y; pr[i][2] = t.z; pr[i][3] = t.w;
            }
#pragma unroll
            for (int ss = 0; ss < 4; ss++) {
                float4 v4 = *(const float4*)&Vs[s4 * 4 + ss][tx * 4];
#pragma unroll
                for (int i = 0; i < 4; i++) {
                    acc[i][0] += pr[i][ss] * v4.x;
                    acc[i][1] += pr[i][ss] * v4.y;
                    acc[i][2] += pr[i][ss] * v4.z;
                    acc[i][3] += pr[i][ss] * v4.w;
                }
            }
        }
    }

    // ---- epilogue: normalize, write [T,B,E] with E = h*64+d ----
#pragma unroll
    for (int i = 0; i < 4; i++) {
        float inv = 1.0f / l[i];
        float4 o = make_float4(acc[i][0] * inv, acc[i][1] * inv,
                               acc[i][2] * inv, acc[i][3] * inv);
        size_t obase = ((size_t)(q0 + ty * 4 + i) * BB + b) * EMB + h * HD + tx * 4;
        *(float4*)(out + obase) = o;
    }
}

// ---------------------------------------------------------------------------
extern "C" void kernel_launch(void* const* d_in, const int* in_sizes, int n_in,
                              void* d_out, int out_size)
{
    const float*    query = (const float*)d_in[0];          // [T,B,E]
    const uint32_t* mask  = (const uint32_t*)d_in[1];       // [B,T] bool widened to 4B
    const float*    W_in  = (const float*)d_in[2];          // [3E,E]
    const float*    b_in  = (const float*)d_in[3];          // [3E]
    const float*    W_out = (const float*)d_in[4];          // [E,E]
    const float*    b_out = (const float*)d_in[5];          // [E]
    float*          out   = (float*)d_out;                  // [T,B,E]

    float *proj, *attn;
    cudaGetSymbolAddress((void**)&proj, g_proj);
    cudaGetSymbolAddress((void**)&attn, g_attn);

    // 1) QKV projection: [4096,3072] = X[4096,1024] @ W_in^T + b_in
    sgemm_nt_bias<<<dim3(E3 / 128, MROWS / 128), 256>>>(
        query, W_in, b_in, proj, MROWS, E3, EMB);

    // 2) flash attention per (b,h), 64-query blocks
    attn_kernel<<<dim3(TSEQ / 64, NH, BB), 256>>>(proj, mask, attn);

    // 3) output projection: [4096,1024] = attn @ W_out^T + b_out
    sgemm_nt_bias<<<dim3(EMB / 128, MROWS / 128), 256>>>(
        attn, W_out, b_out, out, MROWS, EMB, EMB);
}

// round 8
// speedup vs baseline: 1.1175x; 1.1175x over previous
#include <cuda_runtime.h>
#include <cstdint>

#define TSEQ 2048
#define BB   2
#define EMB  1024
#define NH   16
#define HD   64
#define E3   3072
#define MROWS 4096   // T*B
#define SCALING 0.125f

// Scratch (no cudaMalloc allowed) ------------------------------------------
__device__ float g_proj[(size_t)MROWS * E3];   // [T*B, 3E] : q | k | v
__device__ float g_attn[(size_t)MROWS * EMB];  // [T*B, E]  : attention output

// ===========================================================================
// Helpers
// ===========================================================================
__device__ __forceinline__ uint32_t f2tf32(float f) {
    uint32_t r;
    asm("cvt.rna.tf32.f32 %0, %1;" : "=r"(r) : "f"(f));
    return r;
}

// mma.sync m16n8k8 tf32 (base-target PTX, works on sm_103 without 'a')
__device__ __forceinline__ void mma_tf32(float d[4], const uint32_t a[4],
                                         const uint32_t b[2]) {
    asm volatile(
        "mma.sync.aligned.m16n8k8.row.col.f32.tf32.tf32.f32 "
        "{%0,%1,%2,%3}, {%4,%5,%6,%7}, {%8,%9}, {%0,%1,%2,%3};"
        : "+f"(d[0]), "+f"(d[1]), "+f"(d[2]), "+f"(d[3])
        : "r"(a[0]), "r"(a[1]), "r"(a[2]), "r"(a[3]), "r"(b[0]), "r"(b[1]));
}

// ===========================================================================
// TF32 tensor-core GEMM:  C[M,N] = tf32(A[M,K]) * tf32(B[N,K])^T + bias[N]
// 128x128 CTA tile, BK=32, 256 threads (8 warps, warp tile 64x32).
//
// SMEM tile layout: [row][k'] where within each k8 block the 8 k-values are
// stored as float2 pairs (k, k+4) at f2-index f = 4*ks + r, plus XOR swizzle
// p = f ^ ((row&3)<<2). Row stride = 34 words (16 data f2 + 1 pad f2).
// This makes every mma fragment one conflict-free LDS.64, and the loader
// scatter conflict-free STS.32.
// ===========================================================================
#define BK 32
#define TILE_W 34                       // words per row (32 data + 2 pad)
#define TILE_WORDS (128 * TILE_W)       // 4352 words = 17408 B per tile

__device__ __forceinline__ int sw_off(int row, int f, int o) {
    return row * TILE_W + 2 * (f ^ ((row & 3) << 2)) + o;
}

__global__ void __launch_bounds__(256, 2)
mma_gemm_nt_bias(const float* __restrict__ A, const float* __restrict__ B,
                 const float* __restrict__ bias, float* __restrict__ C,
                 int M, int N, int K)
{
    extern __shared__ uint32_t sm[];
    // buffers: [buf][mat]: A0, B0, A1, B1
    uint32_t* As[2] = { sm,                  sm + 2 * TILE_WORDS };
    uint32_t* Bs[2] = { sm + TILE_WORDS,     sm + 3 * TILE_WORDS };

    const int tid  = threadIdx.x;
    const int wid  = tid >> 5;
    const int lane = tid & 31;
    const int q = lane >> 2;      // groupID 0..7
    const int r = lane & 3;       // threadID_in_group 0..3
    const int wm = wid & 1;       // 2 m-blocks of 64
    const int wn = wid >> 1;      // 4 n-blocks of 32

    const int m0 = blockIdx.y * 128;
    const int n0 = blockIdx.x * 128;

    // loader mapping: 4 float4 per matrix per thread per chunk
    int lrow[4], lc[4];
#pragma unroll
    for (int i = 0; i < 4; i++) {
        int f4 = i * 256 + tid;    // 0..1023
        lrow[i] = f4 >> 3;         // 0..127
        lc[i]   = f4 & 7;          // which float4 in the 32-float row
    }
    const float* Abase[4];
    const float* Bbase[4];
#pragma unroll
    for (int i = 0; i < 4; i++) {
        Abase[i] = A + (size_t)(m0 + lrow[i]) * K + lc[i] * 4;
        Bbase[i] = B + (size_t)(n0 + lrow[i]) * K + lc[i] * 4;
    }

    float acc[4][4][4];
#pragma unroll
    for (int mt = 0; mt < 4; mt++)
#pragma unroll
        for (int nt = 0; nt < 4; nt++)
#pragma unroll
            for (int e = 0; e < 4; e++) acc[mt][nt][e] = 0.f;

    const int NCH = K / BK;
    float4 ra[4], rb[4];

#define LDG_CHUNK(c) do {                                                     \
        _Pragma("unroll")                                                     \
        for (int i = 0; i < 4; i++) {                                         \
            ra[i] = *(const float4*)(Abase[i] + (c) * BK);                    \
            rb[i] = *(const float4*)(Bbase[i] + (c) * BK);                    \
        }                                                                     \
    } while (0)

#define STS_CHUNK(buf) do {                                                   \
        _Pragma("unroll")                                                     \
        for (int i = 0; i < 4; i++) {                                         \
            int row = lrow[i];                                                \
            int ks = lc[i] >> 1, o = lc[i] & 1;                               \
            uint32_t* Ad = As[buf]; uint32_t* Bd = Bs[buf];                   \
            const float* av = (const float*)&ra[i];                          \
            const float* bv = (const float*)&rb[i];                          \
            _Pragma("unroll")                                                 \
            for (int j = 0; j < 4; j++) {                                     \
                int off = sw_off(row, 4 * ks + j, o);                         \
                Ad[off] = f2tf32(av[j]);                                      \
                Bd[off] = f2tf32(bv[j]);                                      \
            }                                                                 \
        }                                                                     \
    } while (0)

#define COMPUTE_CHUNK(buf) do {                                               \
        const uint32_t* Asb = As[buf]; const uint32_t* Bsb = Bs[buf];         \
        _Pragma("unroll")                                                     \
        for (int ks = 0; ks < 4; ks++) {                                      \
            int fidx = 4 * ks + r;                                            \
            uint32_t af[4][4];                                                \
            _Pragma("unroll")                                                 \
            for (int mt = 0; mt < 4; mt++) {                                  \
                int rA = wm * 64 + mt * 16 + q;                               \
                int off = sw_off(rA, fidx, 0);                                \
                uint2 lo = *(const uint2*)&Asb[off];                          \
                uint2 hi = *(const uint2*)&Asb[off + 8 * TILE_W];             \
                af[mt][0] = lo.x; af[mt][1] = hi.x;                           \
                af[mt][2] = lo.y; af[mt][3] = hi.y;                           \
            }                                                                 \
            uint32_t bf[4][2];                                                \
            _Pragma("unroll")                                                 \
            for (int nt = 0; nt < 4; nt++) {                                  \
                int rB = wn * 32 + nt * 8 + q;                                \
                int off = sw_off(rB, fidx, 0);                                \
                uint2 b2 = *(const uint2*)&Bsb[off];                          \
                bf[nt][0] = b2.x; bf[nt][1] = b2.y;                           \
            }                                                                 \
            _Pragma("unroll")                                                 \
            for (int mt = 0; mt < 4; mt++)                                    \
                _Pragma("unroll")                                             \
                for (int nt = 0; nt < 4; nt++)                                \
                    mma_tf32(acc[mt][nt], af[mt], bf[nt]);                    \
        }                                                                     \
    } while (0)

    // pipeline: LDG(c+1) | COMPUTE(c) | sync | STS(c+1) | sync
    LDG_CHUNK(0);
    STS_CHUNK(0);
    __syncthreads();

    for (int c = 0; c < NCH; c++) {
        if (c + 1 < NCH) LDG_CHUNK(c + 1);
        COMPUTE_CHUNK(c & 1);
        __syncthreads();
        if (c + 1 < NCH) {
            STS_CHUNK((c + 1) & 1);
            __syncthreads();
        }
    }

    // epilogue: c0,c1 at (row, 2r..2r+1); c2,c3 at (row+8, ...)
#pragma unroll
    for (int nt = 0; nt < 4; nt++) {
        int col = n0 + wn * 32 + nt * 8 + 2 * r;
        float2 bv = *(const float2*)&bias[col];
#pragma unroll
        for (int mt = 0; mt < 4; mt++) {
            int row = m0 + wm * 64 + mt * 16 + q;
            float2 o0 = make_float2(acc[mt][nt][0] + bv.x, acc[mt][nt][1] + bv.y);
            float2 o1 = make_float2(acc[mt][nt][2] + bv.x, acc[mt][nt][3] + bv.y);
            *(float2*)(C + (size_t)row * N + col)        = o0;
            *(float2*)(C + (size_t)(row + 8) * N + col)  = o1;
        }
    }
#undef LDG_CHUNK
#undef STS_CHUNK
#undef COMPUTE_CHUNK
}

// ---------------------------------------------------------------------------
// Flash attention, fp32 (unchanged from passing R5 kernel).
// ---------------------------------------------------------------------------
__device__ __forceinline__ float rmax16(float v) {
    v = fmaxf(v, __shfl_xor_sync(0xffffffffu, v, 8));
    v = fmaxf(v, __shfl_xor_sync(0xffffffffu, v, 4));
    v = fmaxf(v, __shfl_xor_sync(0xffffffffu, v, 2));
    v = fmaxf(v, __shfl_xor_sync(0xffffffffu, v, 1));
    return v;
}
__device__ __forceinline__ float rsum16(float v) {
    v += __shfl_xor_sync(0xffffffffu, v, 8);
    v += __shfl_xor_sync(0xffffffffu, v, 4);
    v += __shfl_xor_sync(0xffffffffu, v, 2);
    v += __shfl_xor_sync(0xffffffffu, v, 1);
    return v;
}

__global__ void __launch_bounds__(256)
attn_kernel(const float* __restrict__ proj, const uint32_t* __restrict__ mask,
            float* __restrict__ out)
{
    __shared__ float Qs[64][64];
    __shared__ float KP[64][64];
    __shared__ float Vs[64][64];

    const int tid = threadIdx.x;
    const int tx = tid & 15, ty = tid >> 4;
    const int qt = blockIdx.x, h = blockIdx.y, b = blockIdx.z;
    const int q0 = qt * 64;

    const int rl = tid >> 2;
    const int jj = tid & 3;

    {
        size_t base = ((size_t)(q0 + rl) * BB + b) * E3 + h * HD;
#pragma unroll
        for (int p = 0; p < 4; p++) {
            int d0 = (jj + p * 4) * 4;
            float4 v = *(const float4*)(proj + base + d0);
            Qs[d0 + 0][rl] = v.x * SCALING;
            Qs[d0 + 1][rl] = v.y * SCALING;
            Qs[d0 + 2][rl] = v.z * SCALING;
            Qs[d0 + 3][rl] = v.w * SCALING;
        }
    }

    float m[4], l[4], acc[4][4];
#pragma unroll
    for (int i = 0; i < 4; i++) {
        m[i] = -1e30f; l[i] = 0.f;
#pragma unroll
        for (int j = 0; j < 4; j++) acc[i][j] = 0.f;
    }

    const uint32_t* mrow = mask + (size_t)b * TSEQ;

    for (int kt = 0; kt < TSEQ / 64; kt++) {
        __syncthreads();
        const int s0 = kt * 64;

        size_t kbase = ((size_t)(s0 + rl) * BB + b) * E3 + EMB + h * HD;
        size_t vbase = kbase + EMB;
#pragma unroll
        for (int p = 0; p < 4; p++) {
            int d0 = (jj + p * 4) * 4;
            float4 kv = *(const float4*)(proj + kbase + d0);
            KP[d0 + 0][rl] = kv.x; KP[d0 + 1][rl] = kv.y;
            KP[d0 + 2][rl] = kv.z; KP[d0 + 3][rl] = kv.w;
            float4 vv = *(const float4*)(proj + vbase + d0);
            *(float4*)&Vs[rl][d0] = vv;
        }
        int nvalid = __syncthreads_count((int)(mrow[s0 + (tid & 63)] == 0u));
        if (nvalid == 0) break;

        float s[4][4];
#pragma unroll
        for (int i = 0; i < 4; i++)
#pragma unroll
            for (int j = 0; j < 4; j++) s[i][j] = 0.f;
#pragma unroll
        for (int d = 0; d < 64; d++) {
            float4 aq = *(const float4*)&Qs[d][ty * 4];
            float4 bk = *(const float4*)&KP[d][tx * 4];
            float av[4] = {aq.x, aq.y, aq.z, aq.w};
            float bv[4] = {bk.x, bk.y, bk.z, bk.w};
#pragma unroll
            for (int i = 0; i < 4; i++)
#pragma unroll
                for (int j = 0; j < 4; j++)
                    s[i][j] += av[i] * bv[j];
        }

        float madd[4];
#pragma unroll
        for (int j = 0; j < 4; j++)
            madd[j] = (mrow[s0 + tx * 4 + j] != 0u) ? -1e30f : 0.f;
#pragma unroll
        for (int i = 0; i < 4; i++)
#pragma unroll
            for (int j = 0; j < 4; j++)
                s[i][j] += madd[j];

        float corr[4];
#pragma unroll
        for (int i = 0; i < 4; i++) {
            float tm = fmaxf(fmaxf(s[i][0], s[i][1]), fmaxf(s[i][2], s[i][3]));
            tm = rmax16(tm);
            float mn = fmaxf(m[i], tm);
            corr[i] = __expf(m[i] - mn);
            m[i] = mn;
            float rs = 0.f;
#pragma unroll
            for (int j = 0; j < 4; j++) {
                float p = __expf(s[i][j] - mn);
                s[i][j] = p;
                rs += p;
            }
            rs = rsum16(rs);
            l[i] = l[i] * corr[i] + rs;
#pragma unroll
            for (int j = 0; j < 4; j++) acc[i][j] *= corr[i];
        }

        __syncthreads();
#pragma unroll
        for (int i = 0; i < 4; i++) {
            float4 pv = make_float4(s[i][0], s[i][1], s[i][2], s[i][3]);
            *(float4*)&KP[ty * 4 + i][tx * 4] = pv;
        }
        __syncthreads();

#pragma unroll
        for (int s4 = 0; s4 < 16; s4++) {
            float pr[4][4];
#pragma unroll
            for (int i = 0; i < 4; i++) {
                float4 t = *(const float4*)&KP[ty * 4 + i][s4 * 4];
                pr[i][0] = t.x; pr[i][1] = t.y; pr[i][2] = t.z; pr[i][3] = t.w;
            }
#pragma unroll
            for (int ss = 0; ss < 4; ss++) {
                float4 v4 = *(const float4*)&Vs[s4 * 4 + ss][tx * 4];
#pragma unroll
                for (int i = 0; i < 4; i++) {
                    acc[i][0] += pr[i][ss] * v4.x;
                    acc[i][1] += pr[i][ss] * v4.y;
                    acc[i][2] += pr[i][ss] * v4.z;
                    acc[i][3] += pr[i][ss] * v4.w;
                }
            }
        }
    }

#pragma unroll
    for (int i = 0; i < 4; i++) {
        float inv = 1.0f / l[i];
        float4 o = make_float4(acc[i][0] * inv, acc[i][1] * inv,
                               acc[i][2] * inv, acc[i][3] * inv);
        size_t obase = ((size_t)(q0 + ty * 4 + i) * BB + b) * EMB + h * HD + tx * 4;
        *(float4*)(out + obase) = o;
    }
}

// ---------------------------------------------------------------------------
extern "C" void kernel_launch(void* const* d_in, const int* in_sizes, int n_in,
                              void* d_out, int out_size)
{
    const float*    query = (const float*)d_in[0];          // [T,B,E]
    const uint32_t* mask  = (const uint32_t*)d_in[1];       // [B,T] bool widened to 4B
    const float*    W_in  = (const float*)d_in[2];          // [3E,E]
    const float*    b_in  = (const float*)d_in[3];          // [3E]
    const float*    W_out = (const float*)d_in[4];          // [E,E]
    const float*    b_out = (const float*)d_in[5];          // [E]
    float*          out   = (float*)d_out;                  // [T,B,E]

    float *proj, *attn;
    cudaGetSymbolAddress((void**)&proj, g_proj);
    cudaGetSymbolAddress((void**)&attn, g_attn);

    const int smem_bytes = 4 * TILE_WORDS * 4;   // 69632 B
    cudaFuncSetAttribute(mma_gemm_nt_bias,
                         cudaFuncAttributeMaxDynamicSharedMemorySize, smem_bytes);

    // 1) QKV projection (tf32 mma.sync): [4096,3072] = X @ W_in^T + b_in
    mma_gemm_nt_bias<<<dim3(E3 / 128, MROWS / 128), 256, smem_bytes>>>(
        query, W_in, b_in, proj, MROWS, E3, EMB);

    // 2) flash attention per (b,h), 64-query blocks (fp32)
    attn_kernel<<<dim3(TSEQ / 64, NH, BB), 256>>>(proj, mask, attn);

    // 3) output projection (tf32 mma.sync): [4096,1024] = attn @ W_out^T + b_out
    mma_gemm_nt_bias<<<dim3(EMB / 128, MROWS / 128), 256, smem_bytes>>>(
        attn, W_out, b_out, out, MROWS, EMB, EMB);
}

// round 9
// speedup vs baseline: 1.5016x; 1.3437x over previous
#include <cuda_runtime.h>
#include <cstdint>

#define TSEQ 2048
#define BB   2
#define EMB  1024
#define NH   16
#define HD   64
#define E3   3072
#define MROWS 4096   // T*B
#define SCALING 0.125f

// Scratch (no cudaMalloc allowed) ------------------------------------------
__device__ float g_proj[(size_t)MROWS * E3];   // [T*B, 3E] : q | k | v
__device__ float g_attn[(size_t)MROWS * EMB];  // [T*B, E]  : attention output

// ===========================================================================
// Helpers
// ===========================================================================
__device__ __forceinline__ uint32_t f2tf32(float f) {
    uint32_t r;
    asm("cvt.rna.tf32.f32 %0, %1;" : "=r"(r) : "f"(f));
    return r;
}

// mma.sync m16n8k8 tf32 (base-target PTX, works on sm_103 without 'a')
__device__ __forceinline__ void mma_tf32(float d[4], const uint32_t a[4],
                                         const uint32_t b[2]) {
    asm volatile(
        "mma.sync.aligned.m16n8k8.row.col.f32.tf32.tf32.f32 "
        "{%0,%1,%2,%3}, {%4,%5,%6,%7}, {%8,%9}, {%0,%1,%2,%3};"
        : "+f"(d[0]), "+f"(d[1]), "+f"(d[2]), "+f"(d[3])
        : "r"(a[0]), "r"(a[1]), "r"(a[2]), "r"(a[3]), "r"(b[0]), "r"(b[1]));
}

// fast e^x on the fma/alu pipes (x <= 0; very negative -> ~0). Max rel err ~2.4e-6.
__device__ __forceinline__ float fast_exp(float x) {
    float y = fmaxf(x * 1.4426950408889634f, -126.0f);   // log2(e)*x, clamped
    float t = y + 12582912.0f;                           // rint via magic
    int   n = __float_as_int(t) - 0x4B400000;
    float f = y - (t - 12582912.0f);                     // f in [-0.5, 0.5]
    float p = 1.3333558146e-3f;
    p = fmaf(p, f, 9.6181291076e-3f);
    p = fmaf(p, f, 5.5504108664e-2f);
    p = fmaf(p, f, 2.4022650696e-1f);
    p = fmaf(p, f, 6.9314718056e-1f);
    p = fmaf(p, f, 1.0f);
    return __int_as_float(__float_as_int(p) + (n << 23));
}

// ===========================================================================
// Shared swizzled tile layout (validated by the GEMM kernel):
// row stride 34 words; within each k8 block, pair (k, k+4) at f2-index
// f = 4*ks + (k&3), word offset o = (k&7)>>2; f XOR'd with (row&3)<<2.
// ===========================================================================
#define BK 32
#define TILE_W 34
#define TILE_WORDS (128 * TILE_W)

__device__ __forceinline__ int sw_off(int row, int f, int o) {
    return row * TILE_W + 2 * (f ^ ((row & 3) << 2)) + o;
}

// store float4 (k0..k0+3 within a 32-wide chunk) for one row, with scale+cvt
__device__ __forceinline__ void sts4(uint32_t* chunk, int row, int k0,
                                     float4 v, float scale) {
    float vv[4] = { v.x, v.y, v.z, v.w };
#pragma unroll
    for (int j = 0; j < 4; j++) {
        int k = k0 + j;
        int f = 4 * (k >> 3) + (k & 3);
        int o = (k & 7) >> 2;
        chunk[sw_off(row, f, o)] = f2tf32(vv[j] * scale);
    }
}

// ===========================================================================
// TF32 tensor-core GEMM:  C[M,N] = tf32(A[M,K]) * tf32(B[N,K])^T + bias[N]
// (unchanged from R8 — passed with rel_err 2.0e-4)
// ===========================================================================
__global__ void __launch_bounds__(256, 2)
mma_gemm_nt_bias(const float* __restrict__ A, const float* __restrict__ B,
                 const float* __restrict__ bias, float* __restrict__ C,
                 int M, int N, int K)
{
    extern __shared__ uint32_t sm[];
    uint32_t* As[2] = { sm,              sm + 2 * TILE_WORDS };
    uint32_t* Bs[2] = { sm + TILE_WORDS, sm + 3 * TILE_WORDS };

    const int tid  = threadIdx.x;
    const int wid  = tid >> 5;
    const int lane = tid & 31;
    const int q = lane >> 2;
    const int r = lane & 3;
    const int wm = wid & 1;
    const int wn = wid >> 1;

    const int m0 = blockIdx.y * 128;
    const int n0 = blockIdx.x * 128;

    int lrow[4], lc[4];
#pragma unroll
    for (int i = 0; i < 4; i++) {
        int f4 = i * 256 + tid;
        lrow[i] = f4 >> 3;
        lc[i]   = f4 & 7;
    }
    const float* Abase[4];
    const float* Bbase[4];
#pragma unroll
    for (int i = 0; i < 4; i++) {
        Abase[i] = A + (size_t)(m0 + lrow[i]) * K + lc[i] * 4;
        Bbase[i] = B + (size_t)(n0 + lrow[i]) * K + lc[i] * 4;
    }

    float acc[4][4][4];
#pragma unroll
    for (int mt = 0; mt < 4; mt++)
#pragma unroll
        for (int nt = 0; nt < 4; nt++)
#pragma unroll
            for (int e = 0; e < 4; e++) acc[mt][nt][e] = 0.f;

    const int NCH = K / BK;
    float4 ra[4], rb[4];

#define LDG_CHUNK(c) do {                                                     \
        _Pragma("unroll")                                                     \
        for (int i = 0; i < 4; i++) {                                         \
            ra[i] = *(const float4*)(Abase[i] + (c) * BK);                    \
            rb[i] = *(const float4*)(Bbase[i] + (c) * BK);                    \
        }                                                                     \
    } while (0)

#define STS_CHUNK(buf) do {                                                   \
        _Pragma("unroll")                                                     \
        for (int i = 0; i < 4; i++) {                                         \
            sts4(As[buf], lrow[i], lc[i] * 4, ra[i], 1.0f);                   \
            sts4(Bs[buf], lrow[i], lc[i] * 4, rb[i], 1.0f);                   \
        }                                                                     \
    } while (0)

#define COMPUTE_CHUNK(buf) do {                                               \
        const uint32_t* Asb = As[buf]; const uint32_t* Bsb = Bs[buf];         \
        _Pragma("unroll")                                                     \
        for (int ks = 0; ks < 4; ks++) {                                      \
            int fidx = 4 * ks + r;                                            \
            uint32_t af[4][4];                                                \
            _Pragma("unroll")                                                 \
            for (int mt = 0; mt < 4; mt++) {                                  \
                int rA = wm * 64 + mt * 16 + q;                               \
                int off = sw_off(rA, fidx, 0);                                \
                uint2 lo = *(const uint2*)&Asb[off];                          \
                uint2 hi = *(const uint2*)&Asb[off + 8 * TILE_W];             \
                af[mt][0] = lo.x; af[mt][1] = hi.x;                           \
                af[mt][2] = lo.y; af[mt][3] = hi.y;                           \
            }                                                                 \
            uint32_t bf[4][2];                                                \
            _Pragma("unroll")                                                 \
            for (int nt = 0; nt < 4; nt++) {                                  \
                int rB = wn * 32 + nt * 8 + q;                                \
                int off = sw_off(rB, fidx, 0);                                \
                uint2 b2 = *(const uint2*)&Bsb[off];                          \
                bf[nt][0] = b2.x; bf[nt][1] = b2.y;                           \
            }                                                                 \
            _Pragma("unroll")                                                 \
            for (int mt = 0; mt < 4; mt++)                                    \
                _Pragma("unroll")                                             \
                for (int nt = 0; nt < 4; nt++)                                \
                    mma_tf32(acc[mt][nt], af[mt], bf[nt]);                    \
        }                                                                     \
    } while (0)

    LDG_CHUNK(0);
    STS_CHUNK(0);
    __syncthreads();

    for (int c = 0; c < NCH; c++) {
        if (c + 1 < NCH) LDG_CHUNK(c + 1);
        COMPUTE_CHUNK(c & 1);
        __syncthreads();
        if (c + 1 < NCH) {
            STS_CHUNK((c + 1) & 1);
            __syncthreads();
        }
    }

#pragma unroll
    for (int nt = 0; nt < 4; nt++) {
        int col = n0 + wn * 32 + nt * 8 + 2 * r;
        float2 bv = *(const float2*)&bias[col];
#pragma unroll
        for (int mt = 0; mt < 4; mt++) {
            int row = m0 + wm * 64 + mt * 16 + q;
            float2 o0 = make_float2(acc[mt][nt][0] + bv.x, acc[mt][nt][1] + bv.y);
            float2 o1 = make_float2(acc[mt][nt][2] + bv.x, acc[mt][nt][3] + bv.y);
            *(float2*)(C + (size_t)row * N + col)       = o0;
            *(float2*)(C + (size_t)(row + 8) * N + col) = o1;
        }
    }
#undef LDG_CHUNK
#undef STS_CHUNK
#undef COMPUTE_CHUNK
}

// ===========================================================================
// Flash attention on tensor cores (tf32 mma.sync), softmax via fast_exp.
// 256 threads (8 warps). Block = 128 queries of one (b,h). Key tiles of 64.
// Warp w owns query rows 16w..16w+15. Smem words:
//   QT[2] 2x(128x34), KT[2] 2x(64x34), VT[2] (V^T: row=d, k=s),
//   PT[2] 2x(128x34), mask floats [64].
// ===========================================================================
#define QT0 0
#define QT1 4352
#define KT0 8704
#define KT1 10880
#define VT0 13056
#define VT1 15232
#define PT0 17408
#define PT1 21760
#define MSK 26112
#define ATTN_SMEM_WORDS (26112 + 64)

__global__ void __launch_bounds__(256, 1)
attn_mma(const float* __restrict__ proj, const uint32_t* __restrict__ mask,
         float* __restrict__ out)
{
    extern __shared__ uint32_t sm[];
    uint32_t* QT[2] = { sm + QT0, sm + QT1 };
    uint32_t* KT[2] = { sm + KT0, sm + KT1 };
    uint32_t* VT[2] = { sm + VT0, sm + VT1 };
    uint32_t* PT[2] = { sm + PT0, sm + PT1 };
    float* msk = (float*)(sm + MSK);

    const int tid  = threadIdx.x;
    const int w    = tid >> 5;
    const int lane = tid & 31;
    const int q = lane >> 2;       // groupID 0..7
    const int r = lane & 3;        // thread-in-group
    const int h = blockIdx.y, b = blockIdx.z;
    const int q0 = blockIdx.x * 128;

    // ---- load Q tile (128 x 64), scaled ----
#pragma unroll
    for (int i = 0; i < 8; i++) {
        int f4 = i * 256 + tid;
        int row = f4 >> 4, fc = f4 & 15;
        float4 v = *(const float4*)(proj +
            ((size_t)(q0 + row) * BB + b) * E3 + h * HD + fc * 4);
        sts4(QT[fc >> 3], row, (fc & 7) * 4, v, SCALING);
    }
    __syncthreads();

    // ---- preload Q fragments (loop-invariant) ----
    uint32_t afq[8][4];
#pragma unroll
    for (int kg = 0; kg < 8; kg++) {
        int fidx = 4 * (kg & 3) + r;
        int rA = w * 16 + q;
        const uint32_t* base = QT[kg >> 2];
        int off = sw_off(rA, fidx, 0);
        uint2 lo = *(const uint2*)&base[off];
        uint2 hi = *(const uint2*)&base[off + 8 * TILE_W];
        afq[kg][0] = lo.x; afq[kg][1] = hi.x;
        afq[kg][2] = lo.y; afq[kg][3] = hi.y;
    }

    float oacc[8][4];
#pragma unroll
    for (int dt = 0; dt < 8; dt++)
#pragma unroll
        for (int e = 0; e < 4; e++) oacc[dt][e] = 0.f;
    float m0 = -1e30f, m1 = -1e30f, l0 = 0.f, l1 = 0.f;

    const uint32_t* mrow = mask + (size_t)b * TSEQ;

    for (int kt = 0; kt < TSEQ / 64; kt++) {
        const int s0 = kt * 64;
        __syncthreads();               // prev-tile PV reads finished

        // ---- load K (row=s, k=d) and V^T (row=d, k=s) ----
#pragma unroll
        for (int i = 0; i < 4; i++) {
            int f4 = i * 256 + tid;
            int srow = f4 >> 4, fc = f4 & 15;
            size_t gb = ((size_t)(s0 + srow) * BB + b) * E3 + h * HD + fc * 4;
            float4 kv = *(const float4*)(proj + gb + EMB);
            sts4(KT[fc >> 3], srow, (fc & 7) * 4, kv, 1.0f);
            float4 vv = *(const float4*)(proj + gb + 2 * EMB);
            {   // scatter transpose: element d = fc*4+j goes to row d, k = srow
                int kl = srow & 31;
                int f = 4 * (kl >> 3) + (kl & 3);
                int o = (kl & 7) >> 2;
                uint32_t* vb = VT[srow >> 5];
                float vvv[4] = { vv.x, vv.y, vv.z, vv.w };
#pragma unroll
                for (int j = 0; j < 4; j++) {
                    int d = fc * 4 + j;
                    vb[sw_off(d, f, o)] = f2tf32(vvv[j]);
                }
            }
        }
        if (tid < 64)
            msk[tid] = (mrow[s0 + tid] != 0u) ? -1e30f : 0.f;
        int nvalid = __syncthreads_count((int)(mrow[s0 + (tid & 63)] == 0u));
        if (nvalid == 0) break;        // monotone pad suffix

        // ---- S = Q K^T : 8 n-tiles x 8 k-steps per warp ----
        float sacc[8][4];
#pragma unroll
        for (int nt = 0; nt < 8; nt++)
#pragma unroll
            for (int e = 0; e < 4; e++) sacc[nt][e] = 0.f;
#pragma unroll
        for (int kg = 0; kg < 8; kg++) {
            int fidx = 4 * (kg & 3) + r;
            const uint32_t* kb = KT[kg >> 2];
#pragma unroll
            for (int nt = 0; nt < 8; nt++) {
                int rB = nt * 8 + q;
                uint2 b2 = *(const uint2*)&kb[sw_off(rB, fidx, 0)];
                uint32_t bf[2] = { b2.x, b2.y };
                mma_tf32(sacc[nt], afq[kg], bf);
            }
        }

        // ---- mask + online softmax (rows q and q+8) ----
        float mx0 = -1e30f, mx1 = -1e30f;
#pragma unroll
        for (int nt = 0; nt < 8; nt++) {
            float mk0 = msk[nt * 8 + 2 * r];
            float mk1 = msk[nt * 8 + 2 * r + 1];
            sacc[nt][0] += mk0; sacc[nt][1] += mk1;
            sacc[nt][2] += mk0; sacc[nt][3] += mk1;
            mx0 = fmaxf(mx0, fmaxf(sacc[nt][0], sacc[nt][1]));
            mx1 = fmaxf(mx1, fmaxf(sacc[nt][2], sacc[nt][3]));
        }
        mx0 = fmaxf(mx0, __shfl_xor_sync(0xffffffffu, mx0, 1));
        mx0 = fmaxf(mx0, __shfl_xor_sync(0xffffffffu, mx0, 2));
        mx1 = fmaxf(mx1, __shfl_xor_sync(0xffffffffu, mx1, 1));
        mx1 = fmaxf(mx1, __shfl_xor_sync(0xffffffffu, mx1, 2));

        float mn0 = fmaxf(m0, mx0), mn1 = fmaxf(m1, mx1);
        float c0 = fast_exp(m0 - mn0), c1 = fast_exp(m1 - mn1);
        m0 = mn0; m1 = mn1;

        float sum0 = 0.f, sum1 = 0.f;
#pragma unroll
        for (int nt = 0; nt < 8; nt++) {
            sacc[nt][0] = fast_exp(sacc[nt][0] - mn0);
            sacc[nt][1] = fast_exp(sacc[nt][1] - mn0);
            sacc[nt][2] = fast_exp(sacc[nt][2] - mn1);
            sacc[nt][3] = fast_exp(sacc[nt][3] - mn1);
            sum0 += sacc[nt][0] + sacc[nt][1];
            sum1 += sacc[nt][2] + sacc[nt][3];
        }
        sum0 += __shfl_xor_sync(0xffffffffu, sum0, 1);
        sum0 += __shfl_xor_sync(0xffffffffu, sum0, 2);
        sum1 += __shfl_xor_sync(0xffffffffu, sum1, 1);
        sum1 += __shfl_xor_sync(0xffffffffu, sum1, 2);

        l0 = l0 * c0 + sum0;
        l1 = l1 * c1 + sum1;
#pragma unroll
        for (int dt = 0; dt < 8; dt++) {
            oacc[dt][0] *= c0; oacc[dt][1] *= c0;
            oacc[dt][2] *= c1; oacc[dt][3] *= c1;
        }

        // ---- store P fragments to smem (own warp's rows only) ----
        {
            int row0 = w * 16 + q;
            int row1 = row0 + 8;
            int jjA = 2 * r, jjB = 2 * r + 1;
            int oA = jjA >> 2, oB = jjB >> 2;
#pragma unroll
            for (int nt = 0; nt < 8; nt++) {
                uint32_t* pb = PT[nt >> 2];
                int fA = 4 * (nt & 3) + (jjA & 3);
                int fB = 4 * (nt & 3) + (jjB & 3);
                pb[sw_off(row0, fA, oA)] = f2tf32(sacc[nt][0]);
                pb[sw_off(row0, fB, oB)] = f2tf32(sacc[nt][1]);
                pb[sw_off(row1, fA, oA)] = f2tf32(sacc[nt][2]);
                pb[sw_off(row1, fB, oB)] = f2tf32(sacc[nt][3]);
            }
        }
        __syncwarp();                  // P rows are warp-private; warp sync suffices

        // ---- O += P V  (A = P rows of this warp, B = V^T) ----
#pragma unroll
        for (int kg = 0; kg < 8; kg++) {
            int fidx = 4 * (kg & 3) + r;
            const uint32_t* pbb = PT[kg >> 2];
            int rA = w * 16 + q;
            int off = sw_off(rA, fidx, 0);
            uint2 lo = *(const uint2*)&pbb[off];
            uint2 hi = *(const uint2*)&pbb[off + 8 * TILE_W];
            uint32_t afp[4] = { lo.x, hi.x, lo.y, hi.y };
            const uint32_t* vb2 = VT[kg >> 2];
#pragma unroll
            for (int dt = 0; dt < 8; dt++) {
                int rB = dt * 8 + q;
                uint2 b2 = *(const uint2*)&vb2[sw_off(rB, fidx, 0)];
                uint32_t bfv[2] = { b2.x, b2.y };
                mma_tf32(oacc[dt], afp, bfv);
            }
        }
    }

    // ---- epilogue: normalize, write [T,B,E] ----
    float inv0 = 1.0f / l0, inv1 = 1.0f / l1;
    int row0 = q0 + w * 16 + q;
#pragma unroll
    for (int dt = 0; dt < 8; dt++) {
        int col = h * HD + dt * 8 + 2 * r;
        float2 o0 = make_float2(oacc[dt][0] * inv0, oacc[dt][1] * inv0);
        float2 o1 = make_float2(oacc[dt][2] * inv1, oacc[dt][3] * inv1);
        *(float2*)(out + ((size_t)row0 * BB + b) * EMB + col)       = o0;
        *(float2*)(out + ((size_t)(row0 + 8) * BB + b) * EMB + col) = o1;
    }
}

// ---------------------------------------------------------------------------
extern "C" void kernel_launch(void* const* d_in, const int* in_sizes, int n_in,
                              void* d_out, int out_size)
{
    const float*    query = (const float*)d_in[0];          // [T,B,E]
    const uint32_t* mask  = (const uint32_t*)d_in[1];       // [B,T] bool widened to 4B
    const float*    W_in  = (const float*)d_in[2];          // [3E,E]
    const float*    b_in  = (const float*)d_in[3];          // [3E]
    const float*    W_out = (const float*)d_in[4];          // [E,E]
    const float*    b_out = (const float*)d_in[5];          // [E]
    float*          out   = (float*)d_out;                  // [T,B,E]

    float *proj, *attn;
    cudaGetSymbolAddress((void**)&proj, g_proj);
    cudaGetSymbolAddress((void**)&attn, g_attn);

    const int gemm_smem = 4 * TILE_WORDS * 4;               // 69632 B
    cudaFuncSetAttribute(mma_gemm_nt_bias,
                         cudaFuncAttributeMaxDynamicSharedMemorySize, gemm_smem);
    const int attn_smem = ATTN_SMEM_WORDS * 4;              // 104704 B
    cudaFuncSetAttribute(attn_mma,
                         cudaFuncAttributeMaxDynamicSharedMemorySize, attn_smem);

    // 1) QKV projection (tf32 mma.sync): [4096,3072] = X @ W_in^T + b_in
    mma_gemm_nt_bias<<<dim3(E3 / 128, MROWS / 128), 256, gemm_smem>>>(
        query, W_in, b_in, proj, MROWS, E3, EMB);

    // 2) flash attention (tf32 mma.sync), 128-query blocks per (b,h)
    attn_mma<<<dim3(TSEQ / 128, NH, BB), 256, attn_smem>>>(proj, mask, attn);

    // 3) output projection (tf32 mma.sync): [4096,1024] = attn @ W_out^T + b_out
    mma_gemm_nt_bias<<<dim3(EMB / 128, MROWS / 128), 256, gemm_smem>>>(
        attn, W_out, b_out, out, MROWS, EMB, EMB);
}

// round 11
// speedup vs baseline: 1.6438x; 1.0947x over previous
#include <cuda_runtime.h>
#include <cstdint>

#define TSEQ 2048
#define BB   2
#define EMB  1024
#define NH   16
#define HD   64
#define E3   3072
#define MROWS 4096   // T*B
#define SCALING 0.125f

// Scratch (no cudaMalloc allowed) ------------------------------------------
__device__ float g_proj[(size_t)MROWS * E3];   // [T*B, 3E] : q | k | v
__device__ float g_attn[(size_t)MROWS * EMB];  // [T*B, E]  : attention output

// ===========================================================================
// Helpers
// ===========================================================================
__device__ __forceinline__ uint32_t f2tf32(float f) {
    uint32_t r;
    asm("cvt.rna.tf32.f32 %0, %1;" : "=r"(r) : "f"(f));
    return r;
}

// mma.sync m16n8k8 tf32 (base-target PTX, works on sm_103 without 'a')
__device__ __forceinline__ void mma_tf32(float d[4], const uint32_t a[4],
                                         const uint32_t b[2]) {
    asm volatile(
        "mma.sync.aligned.m16n8k8.row.col.f32.tf32.tf32.f32 "
        "{%0,%1,%2,%3}, {%4,%5,%6,%7}, {%8,%9}, {%0,%1,%2,%3};"
        : "+f"(d[0]), "+f"(d[1]), "+f"(d[2]), "+f"(d[3])
        : "r"(a[0]), "r"(a[1]), "r"(a[2]), "r"(a[3]), "r"(b[0]), "r"(b[1]));
}

// fast e^x on the fma/alu pipes (x <= 0; very negative -> ~0). Max rel err ~2.4e-6.
__device__ __forceinline__ float fast_exp(float x) {
    float y = fmaxf(x * 1.4426950408889634f, -126.0f);   // log2(e)*x, clamped
    float t = y + 12582912.0f;                           // rint via magic
    int   n = __float_as_int(t) - 0x4B400000;
    float f = y - (t - 12582912.0f);                     // f in [-0.5, 0.5]
    float p = 1.3333558146e-3f;
    p = fmaf(p, f, 9.6181291076e-3f);
    p = fmaf(p, f, 5.5504108664e-2f);
    p = fmaf(p, f, 2.4022650696e-1f);
    p = fmaf(p, f, 6.9314718056e-1f);
    p = fmaf(p, f, 1.0f);
    return __int_as_float(__float_as_int(p) + (n << 23));
}

// ===========================================================================
// Shared swizzled tile layout (validated):
// row stride 34 words; within each k8 block, pair (k, k+4) at f2-index
// f = 4*ks + (k&3), word offset o = (k&7)>>2; f XOR'd with (row&3)<<2.
// ===========================================================================
#define BK 32
#define TILE_W 34
#define TILE_WORDS (128 * TILE_W)

__device__ __forceinline__ int sw_off(int row, int f, int o) {
    return row * TILE_W + 2 * (f ^ ((row & 3) << 2)) + o;
}

// store float4 (k0..k0+3 within a 32-wide chunk) for one row, with scale+cvt
__device__ __forceinline__ void sts4(uint32_t* chunk, int row, int k0,
                                     float4 v, float scale) {
    float vv[4] = { v.x, v.y, v.z, v.w };
#pragma unroll
    for (int j = 0; j < 4; j++) {
        int k = k0 + j;
        int f = 4 * (k >> 3) + (k & 3);
        int o = (k & 7) >> 2;
        chunk[sw_off(row, f, o)] = f2tf32(vv[j] * scale);
    }
}

// ===========================================================================
// TF32 tensor-core GEMM:  C[M,N] = tf32(A[M,K]) * tf32(B[N,K])^T + bias[N]
// 128x128 CTA tile, BK=32, 256 threads (8 warps, warp tile 64x32).
// 3-stage smem ring, ONE barrier per K-chunk:
//   COMPUTE(c) | STS(c+1) | LDG(c+2) | bar
// ===========================================================================
#define NSTAGE 3

__global__ void __launch_bounds__(256, 2)
mma_gemm_nt_bias(const float* __restrict__ A, const float* __restrict__ B,
                 const float* __restrict__ bias, float* __restrict__ C,
                 int M, int N, int K)
{
    extern __shared__ uint32_t sm[];
    uint32_t* As[NSTAGE];
    uint32_t* Bs[NSTAGE];
#pragma unroll
    for (int s = 0; s < NSTAGE; s++) {
        As[s] = sm + s * 2 * TILE_WORDS;
        Bs[s] = sm + s * 2 * TILE_WORDS + TILE_WORDS;
    }

    const int tid  = threadIdx.x;
    const int wid  = tid >> 5;
    const int lane = tid & 31;
    const int q = lane >> 2;
    const int r = lane & 3;
    const int wm = wid & 1;
    const int wn = wid >> 1;

    const int m0 = blockIdx.y * 128;
    const int n0 = blockIdx.x * 128;

    int lrow[4], lc[4];
#pragma unroll
    for (int i = 0; i < 4; i++) {
        int f4 = i * 256 + tid;
        lrow[i] = f4 >> 3;
        lc[i]   = f4 & 7;
    }
    const float* Abase[4];
    const float* Bbase[4];
#pragma unroll
    for (int i = 0; i < 4; i++) {
        Abase[i] = A + (size_t)(m0 + lrow[i]) * K + lc[i] * 4;
        Bbase[i] = B + (size_t)(n0 + lrow[i]) * K + lc[i] * 4;
    }

    float acc[4][4][4];
#pragma unroll
    for (int mt = 0; mt < 4; mt++)
#pragma unroll
        for (int nt = 0; nt < 4; nt++)
#pragma unroll
            for (int e = 0; e < 4; e++) acc[mt][nt][e] = 0.f;

    const int NCH = K / BK;
    float4 ra[4], rb[4];

#define LDG_CHUNK(c) do {                                                     \
        _Pragma("unroll")                                                     \
        for (int i = 0; i < 4; i++) {                                         \
            ra[i] = *(const float4*)(Abase[i] + (c) * BK);                    \
            rb[i] = *(const float4*)(Bbase[i] + (c) * BK);                    \
        }                                                                     \
    } while (0)

#define STS_CHUNK(s) do {                                                     \
        _Pragma("unroll")                                                     \
        for (int i = 0; i < 4; i++) {                                         \
            sts4(As[s], lrow[i], lc[i] * 4, ra[i], 1.0f);                     \
            sts4(Bs[s], lrow[i], lc[i] * 4, rb[i], 1.0f);                     \
        }                                                                     \
    } while (0)

#define COMPUTE_CHUNK(s) do {                                                 \
        const uint32_t* Asb = As[s]; const uint32_t* Bsb = Bs[s];             \
        _Pragma("unroll")                                                     \
        for (int ks = 0; ks < 4; ks++) {                                      \
            int fidx = 4 * ks + r;                                            \
            uint32_t af[4][4];                                                \
            _Pragma("unroll")                                                 \
            for (int mt = 0; mt < 4; mt++) {                                  \
                int rA = wm * 64 + mt * 16 + q;                               \
                int off = sw_off(rA, fidx, 0);                                \
                uint2 lo = *(const uint2*)&Asb[off];                          \
                uint2 hi = *(const uint2*)&Asb[off + 8 * TILE_W];             \
                af[mt][0] = lo.x; af[mt][1] = hi.x;                           \
                af[mt][2] = lo.y; af[mt][3] = hi.y;                           \
            }                                                                 \
            uint32_t bf[4][2];                                                \
            _Pragma("unroll")                                                 \
            for (int nt = 0; nt < 4; nt++) {                                  \
                int rB = wn * 32 + nt * 8 + q;                                \
                int off = sw_off(rB, fidx, 0);                                \
                uint2 b2 = *(const uint2*)&Bsb[off];                          \
                bf[nt][0] = b2.x; bf[nt][1] = b2.y;                           \
            }                                                                 \
            _Pragma("unroll")                                                 \
            for (int mt = 0; mt < 4; mt++)                                    \
                _Pragma("unroll")                                             \
                for (int nt = 0; nt < 4; nt++)                                \
                    mma_tf32(acc[mt][nt], af[mt], bf[nt]);                    \
        }                                                                     \
    } while (0)

    // prologue: stage0 filled+visible, chunk1 in regs
    LDG_CHUNK(0);
    STS_CHUNK(0);
    __syncthreads();
    LDG_CHUNK(1);

    int sc = 0, ss = 1;
    for (int c = 0; c < NCH; c++) {
        COMPUTE_CHUNK(sc);
        if (c + 1 < NCH) STS_CHUNK(ss);
        if (c + 2 < NCH) LDG_CHUNK(c + 2);
        __syncthreads();
        sc = ss;
        ss = (ss + 1 == NSTAGE) ? 0 : ss + 1;
    }

#pragma unroll
    for (int nt = 0; nt < 4; nt++) {
        int col = n0 + wn * 32 + nt * 8 + 2 * r;
        float2 bv = *(const float2*)&bias[col];
#pragma unroll
        for (int mt = 0; mt < 4; mt++) {
            int row = m0 + wm * 64 + mt * 16 + q;
            float2 o0 = make_float2(acc[mt][nt][0] + bv.x, acc[mt][nt][1] + bv.y);
            float2 o1 = make_float2(acc[mt][nt][2] + bv.x, acc[mt][nt][3] + bv.y);
            *(float2*)(C + (size_t)row * N + col)       = o0;
            *(float2*)(C + (size_t)(row + 8) * N + col) = o1;
        }
    }
#undef LDG_CHUNK
#undef STS_CHUNK
#undef COMPUTE_CHUNK
}

// ===========================================================================
// Flash attention on tensor cores (tf32 mma.sync), softmax via fast_exp.
// 256 threads (8 warps). Block = 128 queries of one (b,h). Key tiles of 64.
// PT is ALIASED onto QT (Q lives in registers after the preload), cutting
// smem to ~70KB so 2 CTAs fit per SM (occupancy 12.5% -> 25%).
// ===========================================================================
#define PQ0 0
#define PQ1 4352
#define KT0 8704
#define KT1 10880
#define VT0 13056
#define VT1 15232
#define MSK 17408
#define ATTN_SMEM_WORDS (17408 + 64)

__global__ void __launch_bounds__(256, 2)
attn_mma(const float* __restrict__ proj, const uint32_t* __restrict__ mask,
         float* __restrict__ out)
{
    extern __shared__ uint32_t sm[];
    uint32_t* QT[2] = { sm + PQ0, sm + PQ1 };   // reused as PT after preload
    uint32_t* KT[2] = { sm + KT0, sm + KT1 };
    uint32_t* VT[2] = { sm + VT0, sm + VT1 };
    float* msk = (float*)(sm + MSK);

    const int tid  = threadIdx.x;
    const int w    = tid >> 5;
    const int lane = tid & 31;
    const int q = lane >> 2;       // groupID 0..7
    const int r = lane & 3;        // thread-in-group
    const int h = blockIdx.y, b = blockIdx.z;
    const int q0 = blockIdx.x * 128;

    // ---- load Q tile (128 x 64), scaled ----
#pragma unroll
    for (int i = 0; i < 8; i++) {
        int f4 = i * 256 + tid;
        int row = f4 >> 4, fc = f4 & 15;
        float4 v = *(const float4*)(proj +
            ((size_t)(q0 + row) * BB + b) * E3 + h * HD + fc * 4);
        sts4(QT[fc >> 3], row, (fc & 7) * 4, v, SCALING);
    }
    __syncthreads();

    // ---- preload Q fragments (loop-invariant; QT dead afterwards) ----
    uint32_t afq[8][4];
#pragma unroll
    for (int kg = 0; kg < 8; kg++) {
        int fidx = 4 * (kg & 3) + r;
        int rA = w * 16 + q;
        const uint32_t* base = QT[kg >> 2];
        int off = sw_off(rA, fidx, 0);
        uint2 lo = *(const uint2*)&base[off];
        uint2 hi = *(const uint2*)&base[off + 8 * TILE_W];
        afq[kg][0] = lo.x; afq[kg][1] = hi.x;
        afq[kg][2] = lo.y; afq[kg][3] = hi.y;
    }

    float oacc[8][4];
#pragma unroll
    for (int dt = 0; dt < 8; dt++)
#pragma unroll
        for (int e = 0; e < 4; e++) oacc[dt][e] = 0.f;
    float m0 = -1e30f, m1 = -1e30f, l0 = 0.f, l1 = 0.f;

    const uint32_t* mrow = mask + (size_t)b * TSEQ;

    for (int kt = 0; kt < TSEQ / 64; kt++) {
        const int s0 = kt * 64;
        __syncthreads();               // prev-tile PV + Q-preload reads finished

        // ---- load K (row=s, k=d) and V^T (row=d, k=s) ----
#pragma unroll
        for (int i = 0; i < 4; i++) {
            int f4 = i * 256 + tid;
            int srow = f4 >> 4, fc = f4 & 15;
            size_t gb = ((size_t)(s0 + srow) * BB + b) * E3 + h * HD + fc * 4;
            float4 kv = *(const float4*)(proj + gb + EMB);
            sts4(KT[fc >> 3], srow, (fc & 7) * 4, kv, 1.0f);
            float4 vv = *(const float4*)(proj + gb + 2 * EMB);
            {   // scatter transpose: element d = fc*4+j goes to row d, k = srow
                int kl = srow & 31;
                int f = 4 * (kl >> 3) + (kl & 3);
                int o = (kl & 7) >> 2;
                uint32_t* vb = VT[srow >> 5];
                float vvv[4] = { vv.x, vv.y, vv.z, vv.w };
#pragma unroll
                for (int j = 0; j < 4; j++) {
                    int d = fc * 4 + j;
                    vb[sw_off(d, f, o)] = f2tf32(vvv[j]);
                }
            }
        }
        if (tid < 64)
            msk[tid] = (mrow[s0 + tid] != 0u) ? -1e30f : 0.f;
        int nvalid = __syncthreads_count((int)(mrow[s0 + (tid & 63)] == 0u));
        if (nvalid == 0) break;        // monotone pad suffix

        // ---- S = Q K^T : 8 n-tiles x 8 k-steps per warp ----
        float sacc[8][4];
#pragma unroll
        for (int nt = 0; nt < 8; nt++)
#pragma unroll
            for (int e = 0; e < 4; e++) sacc[nt][e] = 0.f;
#pragma unroll
        for (int kg = 0; kg < 8; kg++) {
            int fidx = 4 * (kg & 3) + r;
            const uint32_t* kb = KT[kg >> 2];
#pragma unroll
            for (int nt = 0; nt < 8; nt++) {
                int rB = nt * 8 + q;
                uint2 b2 = *(const uint2*)&kb[sw_off(rB, fidx, 0)];
                uint32_t bf[2] = { b2.x, b2.y };
                mma_tf32(sacc[nt], afq[kg], bf);
            }
        }

        // ---- mask + online softmax (rows q and q+8) ----
        float mx0 = -1e30f, mx1 = -1e30f;
#pragma unroll
        for (int nt = 0; nt < 8; nt++) {
            float mk0 = msk[nt * 8 + 2 * r];
            float mk1 = msk[nt * 8 + 2 * r + 1];
            sacc[nt][0] += mk0; sacc[nt][1] += mk1;
            sacc[nt][2] += mk0; sacc[nt][3] += mk1;
            mx0 = fmaxf(mx0, fmaxf(sacc[nt][0], sacc[nt][1]));
            mx1 = fmaxf(mx1, fmaxf(sacc[nt][2], sacc[nt][3]));
        }
        mx0 = fmaxf(mx0, __shfl_xor_sync(0xffffffffu, mx0, 1));
        mx0 = fmaxf(mx0, __shfl_xor_sync(0xffffffffu, mx0, 2));
        mx1 = fmaxf(mx1, __shfl_xor_sync(0xffffffffu, mx1, 1));
        mx1 = fmaxf(mx1, __shfl_xor_sync(0xffffffffu, mx1, 2));

        float mn0 = fmaxf(m0, mx0), mn1 = fmaxf(m1, mx1);
        float c0 = fast_exp(m0 - mn0), c1 = fast_exp(m1 - mn1);
        m0 = mn0; m1 = mn1;

        float sum0 = 0.f, sum1 = 0.f;
#pragma unroll
        for (int nt = 0; nt < 8; nt++) {
            sacc[nt][0] = fast_exp(sacc[nt][0] - mn0);
            sacc[nt][1] = fast_exp(sacc[nt][1] - mn0);
            sacc[nt][2] = fast_exp(sacc[nt][2] - mn1);
            sacc[nt][3] = fast_exp(sacc[nt][3] - mn1);
            sum0 += sacc[nt][0] + sacc[nt][1];
            sum1 += sacc[nt][2] + sacc[nt][3];
        }
        sum0 += __shfl_xor_sync(0xffffffffu, sum0, 1);
        sum0 += __shfl_xor_sync(0xffffffffu, sum0, 2);
        sum1 += __shfl_xor_sync(0xffffffffu, sum1, 1);
        sum1 += __shfl_xor_sync(0xffffffffu, sum1, 2);

        l0 = l0 * c0 + sum0;
        l1 = l1 * c1 + sum1;
#pragma unroll
        for (int dt = 0; dt < 8; dt++) {
            oacc[dt][0] *= c0; oacc[dt][1] *= c0;
            oacc[dt][2] *= c1; oacc[dt][3] *= c1;
        }

        // ---- store P fragments to smem (own warp's rows only; aliases QT) ----
        {
            int row0 = w * 16 + q;
            int row1 = row0 + 8;
            int jjA = 2 * r, jjB = 2 * r + 1;
            int oA = jjA >> 2, oB = jjB >> 2;
#pragma unroll
            for (int nt = 0; nt < 8; nt++) {
                uint32_t* pb = QT[nt >> 2];
                int fA = 4 * (nt & 3) + (jjA & 3);
                int fB = 4 * (nt & 3) + (jjB & 3);
                pb[sw_off(row0, fA, oA)] = f2tf32(sacc[nt][0]);
                pb[sw_off(row0, fB, oB)] = f2tf32(sacc[nt][1]);
                pb[sw_off(row1, fA, oA)] = f2tf32(sacc[nt][2]);
                pb[sw_off(row1, fB, oB)] = f2tf32(sacc[nt][3]);
            }
        }
        __syncwarp();                  // P rows are warp-private; warp sync suffices

        // ---- O += P V  (A = P rows of this warp, B = V^T) ----
#pragma unroll
        for (int kg = 0; kg < 8; kg++) {
            int fidx = 4 * (kg & 3) + r;
            const uint32_t* pbb = QT[kg >> 2];
            int rA = w * 16 + q;
            int off = sw_off(rA, fidx, 0);
            uint2 lo = *(const uint2*)&pbb[off];
            uint2 hi = *(const uint2*)&pbb[off + 8 * TILE_W];
            uint32_t afp[4] = { lo.x, hi.x, lo.y, hi.y };
            const uint32_t* vb2 = VT[kg >> 2];
#pragma unroll
            for (int dt = 0; dt < 8; dt++) {
                int rB = dt * 8 + q;
                uint2 b2 = *(const uint2*)&vb2[sw_off(rB, fidx, 0)];
                uint32_t bfv[2] = { b2.x, b2.y };
                mma_tf32(oacc[dt], afp, bfv);
            }
        }
    }

    // ---- epilogue: normalize, write [T,B,E] ----
    float inv0 = 1.0f / l0, inv1 = 1.0f / l1;
    int row0 = q0 + w * 16 + q;
#pragma unroll
    for (int dt = 0; dt < 8; dt++) {
        int col = h * HD + dt * 8 + 2 * r;
        float2 o0 = make_float2(oacc[dt][0] * inv0, oacc[dt][1] * inv0);
        float2 o1 = make_float2(oacc[dt][2] * inv1, oacc[dt][3] * inv1);
        *(float2*)(out + ((size_t)row0 * BB + b) * EMB + col)       = o0;
        *(float2*)(out + ((size_t)(row0 + 8) * BB + b) * EMB + col) = o1;
    }
}

// ---------------------------------------------------------------------------
extern "C" void kernel_launch(void* const* d_in, const int* in_sizes, int n_in,
                              void* d_out, int out_size)
{
    const float*    query = (const float*)d_in[0];          // [T,B,E]
    const uint32_t* mask  = (const uint32_t*)d_in[1];       // [B,T] bool widened to 4B
    const float*    W_in  = (const float*)d_in[2];          // [3E,E]
    const float*    b_in  = (const float*)d_in[3];          // [3E]
    const float*    W_out = (const float*)d_in[4];          // [E,E]
    const float*    b_out = (const float*)d_in[5];          // [E]
    float*          out   = (float*)d_out;                  // [T,B,E]

    float *proj, *attn;
    cudaGetSymbolAddress((void**)&proj, g_proj);
    cudaGetSymbolAddress((void**)&attn, g_attn);

    const int gemm_smem = NSTAGE * 2 * TILE_WORDS * 4;      // 104448 B
    cudaFuncSetAttribute(mma_gemm_nt_bias,
                         cudaFuncAttributeMaxDynamicSharedMemorySize, gemm_smem);
    const int attn_smem = ATTN_SMEM_WORDS * 4;              // 69888 B
    cudaFuncSetAttribute(attn_mma,
                         cudaFuncAttributeMaxDynamicSharedMemorySize, attn_smem);

    // 1) QKV projection (tf32 mma.sync): [4096,3072] = X @ W_in^T + b_in
    mma_gemm_nt_bias<<<dim3(E3 / 128, MROWS / 128), 256, gemm_smem>>>(
        query, W_in, b_in, proj, MROWS, E3, EMB);

    // 2) flash attention (tf32 mma.sync), 128-query blocks per (b,h)
    attn_mma<<<dim3(TSEQ / 128, NH, BB), 256, attn_smem>>>(proj, mask, attn);

    // 3) output projection (tf32 mma.sync): [4096,1024] = attn @ W_out^T + b_out
    mma_gemm_nt_bias<<<dim3(EMB / 128, MROWS / 128), 256, gemm_smem>>>(
        attn, W_out, b_out, out, MROWS, EMB, EMB);
}

// round 12
// speedup vs baseline: 2.5662x; 1.5612x over previous
#include <cuda_runtime.h>
#include <cstdint>

#define TSEQ 2048
#define BB   2
#define EMB  1024
#define NH   16
#define HD   64
#define E3   3072
#define MROWS 4096   // T*B
#define SCALING 0.125f

// Scratch (no cudaMalloc allowed) ------------------------------------------
__device__ float g_proj[(size_t)MROWS * E3];   // [T*B, 3E] : q | k | v
__device__ float g_attn[(size_t)MROWS * EMB];  // [T*B, E]  : attention output

// ===========================================================================
// Helpers
// ===========================================================================
__device__ __forceinline__ uint32_t smem_u32(const void* p) {
    uint32_t a;
    asm("{ .reg .u64 t; cvta.to.shared.u64 t, %1; cvt.u32.u64 %0, t; }"
        : "=r"(a) : "l"(p));
    return a;
}
__device__ __forceinline__ uint32_t f2tf32(float f) {
    uint32_t r;
    asm("cvt.rna.tf32.f32 %0, %1;" : "=r"(r) : "f"(f));
    return r;
}

// mma.sync m16n8k8 tf32 (base-target PTX, works on sm_103 without 'a')
__device__ __forceinline__ void mma_tf32(float d[4], const uint32_t a[4],
                                         const uint32_t b[2]) {
    asm volatile(
        "mma.sync.aligned.m16n8k8.row.col.f32.tf32.tf32.f32 "
        "{%0,%1,%2,%3}, {%4,%5,%6,%7}, {%8,%9}, {%0,%1,%2,%3};"
        : "+f"(d[0]), "+f"(d[1]), "+f"(d[2]), "+f"(d[3])
        : "r"(a[0]), "r"(a[1]), "r"(a[2]), "r"(a[3]), "r"(b[0]), "r"(b[1]));
}

// fast e^x on the fma/alu pipes (x <= 0; very negative -> ~0). Max rel err ~2.4e-6.
__device__ __forceinline__ float fast_exp(float x) {
    float y = fmaxf(x * 1.4426950408889634f, -126.0f);   // log2(e)*x, clamped
    float t = y + 12582912.0f;                           // rint via magic
    int   n = __float_as_int(t) - 0x4B400000;
    float f = y - (t - 12582912.0f);                     // f in [-0.5, 0.5]
    float p = 1.3333558146e-3f;
    p = fmaf(p, f, 9.6181291076e-3f);
    p = fmaf(p, f, 5.5504108664e-2f);
    p = fmaf(p, f, 2.4022650696e-1f);
    p = fmaf(p, f, 6.9314718056e-1f);
    p = fmaf(p, f, 1.0f);
    return __int_as_float(__float_as_int(p) + (n << 23));
}

#define CP_ASYNC16(dst, src) \
    asm volatile("cp.async.cg.shared.global [%0], [%1], 16;" \
                 :: "r"(dst), "l"(src) : "memory")
#define CP_COMMIT() asm volatile("cp.async.commit_group;" ::: "memory")
#define CP_WAIT1()  asm volatile("cp.async.wait_group 1;" ::: "memory")

// ===========================================================================
// GEMM smem layout (cp.async-compatible):
// element (row, k) of a 128x32 fp32 chunk at word  row*32 + ((k>>2 ^ (row&7))<<2) + (k&3)
// 16 KB per tile, no padding. Fragment LDS.32 banks = 4q+r perm -> conflict-free.
// ===========================================================================
#define BK 32
#define CH_WORDS 4096                 // 128 rows x 32 words
#define GS_STAGE (2 * CH_WORDS)       // A + B per stage
#define GS_NSTAGE 3

__global__ void __launch_bounds__(256, 2)
mma_gemm_nt_bias(const float* __restrict__ A, const float* __restrict__ B,
                 const float* __restrict__ bias, float* __restrict__ C,
                 int M, int N, int K)
{
    extern __shared__ uint32_t sm[];
    const uint32_t smem_base = smem_u32(sm);

    const int tid  = threadIdx.x;
    const int wid  = tid >> 5;
    const int lane = tid & 31;
    const int q = lane >> 2;
    const int r = lane & 3;
    const int wm = wid & 1;
    const int wn = wid >> 1;

    const int m0 = blockIdx.y * 128;
    const int n0 = blockIdx.x * 128;

    // loader mapping: 4x 16B groups per matrix per thread per chunk
    const float* a_src[4];
    const float* b_src[4];
    uint32_t goff[4];                  // byte offset within a chunk tile
#pragma unroll
    for (int i = 0; i < 4; i++) {
        int f4  = i * 256 + tid;       // 0..1023
        int row = f4 >> 3;             // 0..127
        int k4  = f4 & 7;              // 16B group in row
        a_src[i] = A + (size_t)(m0 + row) * K + k4 * 4;
        b_src[i] = B + (size_t)(n0 + row) * K + k4 * 4;
        goff[i]  = (uint32_t)(row * 32 + ((k4 ^ (row & 7)) << 2)) * 4;
    }

    float acc[4][4][4];
#pragma unroll
    for (int mt = 0; mt < 4; mt++)
#pragma unroll
        for (int nt = 0; nt < 4; nt++)
#pragma unroll
            for (int e = 0; e < 4; e++) acc[mt][nt][e] = 0.f;

    const int NCH = K / BK;

#define ISSUE_CHUNK(c, s) do {                                                \
        uint32_t a_dst = smem_base + (uint32_t)((s) * GS_STAGE) * 4;          \
        uint32_t b_dst = a_dst + CH_WORDS * 4;                                \
        _Pragma("unroll")                                                     \
        for (int i = 0; i < 4; i++) {                                         \
            CP_ASYNC16(a_dst + goff[i], a_src[i] + (c) * BK);                 \
            CP_ASYNC16(b_dst + goff[i], b_src[i] + (c) * BK);                 \
        }                                                                     \
    } while (0)

#define COMPUTE_CHUNK(s) do {                                                 \
        const uint32_t* Asb = sm + (s) * GS_STAGE;                            \
        const uint32_t* Bsb = Asb + CH_WORDS;                                 \
        _Pragma("unroll")                                                     \
        for (int ks = 0; ks < 4; ks++) {                                      \
            int o0 = (((2 * ks) ^ q) << 2) + r;                               \
            int o1 = (((2 * ks + 1) ^ q) << 2) + r;                           \
            uint32_t af[4][4];                                                \
            _Pragma("unroll")                                                 \
            for (int mt = 0; mt < 4; mt++) {                                  \
                int base = (wm * 64 + mt * 16 + q) * 32;                      \
                af[mt][0] = Asb[base + o0];                                   \
                af[mt][1] = Asb[base + 256 + o0];                             \
                af[mt][2] = Asb[base + o1];                                   \
                af[mt][3] = Asb[base + 256 + o1];                             \
            }                                                                 \
            uint32_t bf[4][2];                                                \
            _Pragma("unroll")                                                 \
            for (int nt = 0; nt < 4; nt++) {                                  \
                int base = (wn * 32 + nt * 8 + q) * 32;                       \
                bf[nt][0] = Bsb[base + o0];                                   \
                bf[nt][1] = Bsb[base + o1];                                   \
            }                                                                 \
            _Pragma("unroll")                                                 \
            for (int mt = 0; mt < 4; mt++)                                    \
                _Pragma("unroll")                                             \
                for (int nt = 0; nt < 4; nt++)                                \
                    mma_tf32(acc[mt][nt], af[mt], bf[nt]);                    \
        }                                                                     \
    } while (0)

    // prologue: 2 chunks in flight
    ISSUE_CHUNK(0, 0); CP_COMMIT();
    ISSUE_CHUNK(1, 1); CP_COMMIT();

    int sc = 0;
    for (int c = 0; c < NCH; c++) {
        CP_WAIT1();                    // chunk c landed (c+1 may be pending)
        __syncthreads();               // visible to all warps
        COMPUTE_CHUNK(sc);
        if (c + 2 < NCH) {
            int ns = sc + 2; if (ns >= GS_NSTAGE) ns -= GS_NSTAGE;
            ISSUE_CHUNK(c + 2, ns);
        }
        CP_COMMIT();                   // always commit (possibly empty group)
        sc = (sc + 1 == GS_NSTAGE) ? 0 : sc + 1;
    }

    // epilogue: add bias, write
#pragma unroll
    for (int nt = 0; nt < 4; nt++) {
        int col = n0 + wn * 32 + nt * 8 + 2 * r;
        float2 bv = *(const float2*)&bias[col];
#pragma unroll
        for (int mt = 0; mt < 4; mt++) {
            int row = m0 + wm * 64 + mt * 16 + q;
            float2 o0 = make_float2(acc[mt][nt][0] + bv.x, acc[mt][nt][1] + bv.y);
            float2 o1 = make_float2(acc[mt][nt][2] + bv.x, acc[mt][nt][3] + bv.y);
            *(float2*)(C + (size_t)row * N + col)       = o0;
            *(float2*)(C + (size_t)(row + 8) * N + col) = o1;
        }
    }
#undef ISSUE_CHUNK
#undef COMPUTE_CHUNK
}

// ===========================================================================
// Attention smem layout (unchanged, pair-swizzled):
// row stride 34 words; pair (k, k+4) at f2-index f = 4*(k>>3) + (k&3),
// word o = (k&7)>>2; f XOR'd with (row&3)<<2.
// ===========================================================================
#define TILE_W 34

__device__ __forceinline__ int sw_off(int row, int f, int o) {
    return row * TILE_W + 2 * (f ^ ((row & 3) << 2)) + o;
}

__device__ __forceinline__ void sts4(uint32_t* chunk, int row, int k0,
                                     float4 v, float scale) {
    float vv[4] = { v.x, v.y, v.z, v.w };
#pragma unroll
    for (int j = 0; j < 4; j++) {
        int k = k0 + j;
        int f = 4 * (k >> 3) + (k & 3);
        int o = (k & 7) >> 2;
        chunk[sw_off(row, f, o)] = f2tf32(vv[j] * scale);
    }
}

// ===========================================================================
// Flash attention on tensor cores (tf32 mma.sync), softmax via fast_exp.
// 256 threads (8 warps). Block = 128 queries of one (b,h). Key tiles of 64.
// PT aliased onto QT; ~70KB smem -> 2 CTAs/SM. (Unchanged from R11.)
// ===========================================================================
#define PQ0 0
#define PQ1 4352
#define KT0 8704
#define KT1 10880
#define VT0 13056
#define VT1 15232
#define MSK 17408
#define ATTN_SMEM_WORDS (17408 + 64)

__global__ void __launch_bounds__(256, 2)
attn_mma(const float* __restrict__ proj, const uint32_t* __restrict__ mask,
         float* __restrict__ out)
{
    extern __shared__ uint32_t sm[];
    uint32_t* QT[2] = { sm + PQ0, sm + PQ1 };   // reused as PT after preload
    uint32_t* KT[2] = { sm + KT0, sm + KT1 };
    uint32_t* VT[2] = { sm + VT0, sm + VT1 };
    float* msk = (float*)(sm + MSK);

    const int tid  = threadIdx.x;
    const int w    = tid >> 5;
    const int lane = tid & 31;
    const int q = lane >> 2;
    const int r = lane & 3;
    const int h = blockIdx.y, b = blockIdx.z;
    const int q0 = blockIdx.x * 128;

    // ---- load Q tile (128 x 64), scaled ----
#pragma unroll
    for (int i = 0; i < 8; i++) {
        int f4 = i * 256 + tid;
        int row = f4 >> 4, fc = f4 & 15;
        float4 v = *(const float4*)(proj +
            ((size_t)(q0 + row) * BB + b) * E3 + h * HD + fc * 4);
        sts4(QT[fc >> 3], row, (fc & 7) * 4, v, SCALING);
    }
    __syncthreads();

    // ---- preload Q fragments (loop-invariant; QT dead afterwards) ----
    uint32_t afq[8][4];
#pragma unroll
    for (int kg = 0; kg < 8; kg++) {
        int fidx = 4 * (kg & 3) + r;
        int rA = w * 16 + q;
        const uint32_t* base = QT[kg >> 2];
        int off = sw_off(rA, fidx, 0);
        uint2 lo = *(const uint2*)&base[off];
        uint2 hi = *(const uint2*)&base[off + 8 * TILE_W];
        afq[kg][0] = lo.x; afq[kg][1] = hi.x;
        afq[kg][2] = lo.y; afq[kg][3] = hi.y;
    }

    float oacc[8][4];
#pragma unroll
    for (int dt = 0; dt < 8; dt++)
#pragma unroll
        for (int e = 0; e < 4; e++) oacc[dt][e] = 0.f;
    float m0 = -1e30f, m1 = -1e30f, l0 = 0.f, l1 = 0.f;

    const uint32_t* mrow = mask + (size_t)b * TSEQ;

    for (int kt = 0; kt < TSEQ / 64; kt++) {
        const int s0 = kt * 64;
        __syncthreads();               // prev-tile PV + Q-preload reads finished

        // ---- load K (row=s, k=d) and V^T (row=d, k=s) ----
#pragma unroll
        for (int i = 0; i < 4; i++) {
            int f4 = i * 256 + tid;
            int srow = f4 >> 4, fc = f4 & 15;
            size_t gb = ((size_t)(s0 + srow) * BB + b) * E3 + h * HD + fc * 4;
            float4 kv = *(const float4*)(proj + gb + EMB);
            sts4(KT[fc >> 3], srow, (fc & 7) * 4, kv, 1.0f);
            float4 vv = *(const float4*)(proj + gb + 2 * EMB);
            {   // scatter transpose: element d = fc*4+j goes to row d, k = srow
                int kl = srow & 31;
                int f = 4 * (kl >> 3) + (kl & 3);
                int o = (kl & 7) >> 2;
                uint32_t* vb = VT[srow >> 5];
                float vvv[4] = { vv.x, vv.y, vv.z, vv.w };
#pragma unroll
                for (int j = 0; j < 4; j++) {
                    int d = fc * 4 + j;
                    vb[sw_off(d, f, o)] = f2tf32(vvv[j]);
                }
            }
        }
        if (tid < 64)
            msk[tid] = (mrow[s0 + tid] != 0u) ? -1e30f : 0.f;
        int nvalid = __syncthreads_count((int)(mrow[s0 + (tid & 63)] == 0u));
        if (nvalid == 0) break;        // monotone pad suffix

        // ---- S = Q K^T ----
        float sacc[8][4];
#pragma unroll
        for (int nt = 0; nt < 8; nt++)
#pragma unroll
            for (int e = 0; e < 4; e++) sacc[nt][e] = 0.f;
#pragma unroll
        for (int kg = 0; kg < 8; kg++) {
            int fidx = 4 * (kg & 3) + r;
            const uint32_t* kb = KT[kg >> 2];
#pragma unroll
            for (int nt = 0; nt < 8; nt++) {
                int rB = nt * 8 + q;
                uint2 b2 = *(const uint2*)&kb[sw_off(rB, fidx, 0)];
                uint32_t bf[2] = { b2.x, b2.y };
                mma_tf32(sacc[nt], afq[kg], bf);
            }
        }

        // ---- mask + online softmax (rows q and q+8) ----
        float mx0 = -1e30f, mx1 = -1e30f;
#pragma unroll
        for (int nt = 0; nt < 8; nt++) {
            float mk0 = msk[nt * 8 + 2 * r];
            float mk1 = msk[nt * 8 + 2 * r + 1];
            sacc[nt][0] += mk0; sacc[nt][1] += mk1;
            sacc[nt][2] += mk0; sacc[nt][3] += mk1;
            mx0 = fmaxf(mx0, fmaxf(sacc[nt][0], sacc[nt][1]));
            mx1 = fmaxf(mx1, fmaxf(sacc[nt][2], sacc[nt][3]));
        }
        mx0 = fmaxf(mx0, __shfl_xor_sync(0xffffffffu, mx0, 1));
        mx0 = fmaxf(mx0, __shfl_xor_sync(0xffffffffu, mx0, 2));
        mx1 = fmaxf(mx1, __shfl_xor_sync(0xffffffffu, mx1, 1));
        mx1 = fmaxf(mx1, __shfl_xor_sync(0xffffffffu, mx1, 2));

        float mn0 = fmaxf(m0, mx0), mn1 = fmaxf(m1, mx1);
        float c0 = fast_exp(m0 - mn0), c1 = fast_exp(m1 - mn1);
        m0 = mn0; m1 = mn1;

        float sum0 = 0.f, sum1 = 0.f;
#pragma unroll
        for (int nt = 0; nt < 8; nt++) {
            sacc[nt][0] = fast_exp(sacc[nt][0] - mn0);
            sacc[nt][1] = fast_exp(sacc[nt][1] - mn0);
            sacc[nt][2] = fast_exp(sacc[nt][2] - mn1);
            sacc[nt][3] = fast_exp(sacc[nt][3] - mn1);
            sum0 += sacc[nt][0] + sacc[nt][1];
            sum1 += sacc[nt][2] + sacc[nt][3];
        }
        sum0 += __shfl_xor_sync(0xffffffffu, sum0, 1);
        sum0 += __shfl_xor_sync(0xffffffffu, sum0, 2);
        sum1 += __shfl_xor_sync(0xffffffffu, sum1, 1);
        sum1 += __shfl_xor_sync(0xffffffffu, sum1, 2);

        l0 = l0 * c0 + sum0;
        l1 = l1 * c1 + sum1;
#pragma unroll
        for (int dt = 0; dt < 8; dt++) {
            oacc[dt][0] *= c0; oacc[dt][1] *= c0;
            oacc[dt][2] *= c1; oacc[dt][3] *= c1;
        }

        // ---- store P fragments to smem (own warp's rows only; aliases QT) ----
        {
            int row0 = w * 16 + q;
            int row1 = row0 + 8;
            int jjA = 2 * r, jjB = 2 * r + 1;
            int oA = jjA >> 2, oB = jjB >> 2;
#pragma unroll
            for (int nt = 0; nt < 8; nt++) {
                uint32_t* pb = QT[nt >> 2];
                int fA = 4 * (nt & 3) + (jjA & 3);
                int fB = 4 * (nt & 3) + (jjB & 3);
                pb[sw_off(row0, fA, oA)] = f2tf32(sacc[nt][0]);
                pb[sw_off(row0, fB, oB)] = f2tf32(sacc[nt][1]);
                pb[sw_off(row1, fA, oA)] = f2tf32(sacc[nt][2]);
                pb[sw_off(row1, fB, oB)] = f2tf32(sacc[nt][3]);
            }
        }
        __syncwarp();                  // P rows are warp-private

        // ---- O += P V ----
#pragma unroll
        for (int kg = 0; kg < 8; kg++) {
            int fidx = 4 * (kg & 3) + r;
            const uint32_t* pbb = QT[kg >> 2];
            int rA = w * 16 + q;
            int off = sw_off(rA, fidx, 0);
            uint2 lo = *(const uint2*)&pbb[off];
            uint2 hi = *(const uint2*)&pbb[off + 8 * TILE_W];
            uint32_t afp[4] = { lo.x, hi.x, lo.y, hi.y };
            const uint32_t* vb2 = VT[kg >> 2];
#pragma unroll
            for (int dt = 0; dt < 8; dt++) {
                int rB = dt * 8 + q;
                uint2 b2 = *(const uint2*)&vb2[sw_off(rB, fidx, 0)];
                uint32_t bfv[2] = { b2.x, b2.y };
                mma_tf32(oacc[dt], afp, bfv);
            }
        }
    }

    // ---- epilogue: normalize, write [T,B,E] ----
    float inv0 = 1.0f / l0, inv1 = 1.0f / l1;
    int row0 = q0 + w * 16 + q;
#pragma unroll
    for (int dt = 0; dt < 8; dt++) {
        int col = h * HD + dt * 8 + 2 * r;
        float2 o0 = make_float2(oacc[dt][0] * inv0, oacc[dt][1] * inv0);
        float2 o1 = make_float2(oacc[dt][2] * inv1, oacc[dt][3] * inv1);
        *(float2*)(out + ((size_t)row0 * BB + b) * EMB + col)       = o0;
        *(float2*)(out + ((size_t)(row0 + 8) * BB + b) * EMB + col) = o1;
    }
}

// ---------------------------------------------------------------------------
extern "C" void kernel_launch(void* const* d_in, const int* in_sizes, int n_in,
                              void* d_out, int out_size)
{
    const float*    query = (const float*)d_in[0];          // [T,B,E]
    const uint32_t* mask  = (const uint32_t*)d_in[1];       // [B,T] bool widened to 4B
    const float*    W_in  = (const float*)d_in[2];          // [3E,E]
    const float*    b_in  = (const float*)d_in[3];          // [3E]
    const float*    W_out = (const float*)d_in[4];          // [E,E]
    const float*    b_out = (const float*)d_in[5];          // [E]
    float*          out   = (float*)d_out;                  // [T,B,E]

    float *proj, *attn;
    cudaGetSymbolAddress((void**)&proj, g_proj);
    cudaGetSymbolAddress((void**)&attn, g_attn);

    const int gemm_smem = GS_NSTAGE * GS_STAGE * 4;         // 98304 B
    cudaFuncSetAttribute(mma_gemm_nt_bias,
                         cudaFuncAttributeMaxDynamicSharedMemorySize, gemm_smem);
    const int attn_smem = ATTN_SMEM_WORDS * 4;              // 69888 B
    cudaFuncSetAttribute(attn_mma,
                         cudaFuncAttributeMaxDynamicSharedMemorySize, attn_smem);

    // 1) QKV projection (tf32 mma.sync + cp.async): [4096,3072] = X @ W_in^T + b_in
    mma_gemm_nt_bias<<<dim3(E3 / 128, MROWS / 128), 256, gemm_smem>>>(
        query, W_in, b_in, proj, MROWS, E3, EMB);

    // 2) flash attention (tf32 mma.sync), 128-query blocks per (b,h)
    attn_mma<<<dim3(TSEQ / 128, NH, BB), 256, attn_smem>>>(proj, mask, attn);

    // 3) output projection: [4096,1024] = attn @ W_out^T + b_out
    mma_gemm_nt_bias<<<dim3(EMB / 128, MROWS / 128), 256, gemm_smem>>>(
        attn, W_out, b_out, out, MROWS, EMB, EMB);
}

// round 14
// speedup vs baseline: 2.7633x; 1.0768x over previous
#include <cuda_runtime.h>
#include <cstdint>

#define TSEQ 2048
#define BB   2
#define EMB  1024
#define NH   16
#define HD   64
#define E3   3072
#define MROWS 4096   // T*B
#define SCALING 0.125f

// Scratch (no cudaMalloc allowed) ------------------------------------------
__device__ float g_proj[(size_t)MROWS * E3];    // [T*B, 3E] : q | k | v
__device__ float g_attn[(size_t)MROWS * EMB];   // [T*B, E]
__device__ float g_qr[(size_t)MROWS * EMB];     // tf32-rounded query
__device__ float g_winr[(size_t)E3 * EMB];      // tf32-rounded W_in
__device__ float g_woutr[(size_t)EMB * EMB];    // tf32-rounded W_out

// ===========================================================================
// Helpers
// ===========================================================================
__device__ __forceinline__ uint32_t smem_u32(const void* p) {
    uint32_t a;
    asm("{ .reg .u64 t; cvta.to.shared.u64 t, %1; cvt.u32.u64 %0, t; }"
        : "=r"(a) : "l"(p));
    return a;
}
__device__ __forceinline__ uint32_t f2tf32(float f) {
    uint32_t r;
    asm("cvt.rna.tf32.f32 %0, %1;" : "=r"(r) : "f"(f));
    return r;
}
__device__ __forceinline__ float f2tf32f(float f) {
    return __uint_as_float(f2tf32(f));
}

// mma.sync m16n8k8 tf32 (base-target PTX, works on sm_103 without 'a')
__device__ __forceinline__ void mma_tf32(float d[4], const uint32_t a[4],
                                         const uint32_t b[2]) {
    asm volatile(
        "mma.sync.aligned.m16n8k8.row.col.f32.tf32.tf32.f32 "
        "{%0,%1,%2,%3}, {%4,%5,%6,%7}, {%8,%9}, {%0,%1,%2,%3};"
        : "+f"(d[0]), "+f"(d[1]), "+f"(d[2]), "+f"(d[3])
        : "r"(a[0]), "r"(a[1]), "r"(a[2]), "r"(a[3]), "r"(b[0]), "r"(b[1]));
}

// fast e^x on the fma/alu pipes (x <= 0; very negative -> ~0). Max rel err ~2.4e-6.
__device__ __forceinline__ float fast_exp(float x) {
    float y = fmaxf(x * 1.4426950408889634f, -126.0f);
    float t = y + 12582912.0f;
    int   n = __float_as_int(t) - 0x4B400000;
    float f = y - (t - 12582912.0f);
    float p = 1.3333558146e-3f;
    p = fmaf(p, f, 9.6181291076e-3f);
    p = fmaf(p, f, 5.5504108664e-2f);
    p = fmaf(p, f, 2.4022650696e-1f);
    p = fmaf(p, f, 6.9314718056e-1f);
    p = fmaf(p, f, 1.0f);
    return __int_as_float(__float_as_int(p) + (n << 23));
}

#define CP_ASYNC16(dst, src) \
    asm volatile("cp.async.cg.shared.global [%0], [%1], 16;" \
                 :: "r"(dst), "l"(src) : "memory")
#define CP_COMMIT() asm volatile("cp.async.commit_group;" ::: "memory")
#define CP_WAIT1()  asm volatile("cp.async.wait_group 1;" ::: "memory")
#define CP_WAIT0()  asm volatile("cp.async.wait_group 0;" ::: "memory")

// ===========================================================================
// Pre-round: dst = tf32_rna(src), elementwise (makes later HW truncation lossless)
// ===========================================================================
__global__ void round_tf32_kernel(const float* __restrict__ src,
                                  float* __restrict__ dst, int n4)
{
    int i = blockIdx.x * blockDim.x + threadIdx.x;
    if (i < n4) {
        float4 v = ((const float4*)src)[i];
        ((uint4*)dst)[i] = make_uint4(f2tf32(v.x), f2tf32(v.y),
                                      f2tf32(v.z), f2tf32(v.w));
    }
}

// ===========================================================================
// GEMM smem layout (cp.async-compatible):
// element (row, k) of a RxB32 fp32 chunk at word  row*32 + ((k>>2 ^ (row&7))<<2) + (k&3)
// ===========================================================================
#define BK 32
#define CH_WORDS 4096                 // 128 rows x 32 words
#define GS_STAGE (2 * CH_WORDS)
#define GS_NSTAGE 3

__global__ void __launch_bounds__(256, 2)
mma_gemm_nt_bias(const float* __restrict__ A, const float* __restrict__ B,
                 const float* __restrict__ bias, float* __restrict__ C,
                 int M, int N, int K, int round_c)
{
    extern __shared__ uint32_t sm[];
    const uint32_t smem_base = smem_u32(sm);

    const int tid  = threadIdx.x;
    const int wid  = tid >> 5;
    const int lane = tid & 31;
    const int q = lane >> 2;
    const int r = lane & 3;
    const int wm = wid & 1;
    const int wn = wid >> 1;

    const int m0 = blockIdx.y * 128;
    const int n0 = blockIdx.x * 128;

    const float* a_src[4];
    const float* b_src[4];
    uint32_t goff[4];
#pragma unroll
    for (int i = 0; i < 4; i++) {
        int f4  = i * 256 + tid;
        int row = f4 >> 3;
        int k4  = f4 & 7;
        a_src[i] = A + (size_t)(m0 + row) * K + k4 * 4;
        b_src[i] = B + (size_t)(n0 + row) * K + k4 * 4;
        goff[i]  = (uint32_t)(row * 32 + ((k4 ^ (row & 7)) << 2)) * 4;
    }

    float acc[4][4][4];
#pragma unroll
    for (int mt = 0; mt < 4; mt++)
#pragma unroll
        for (int nt = 0; nt < 4; nt++)
#pragma unroll
            for (int e = 0; e < 4; e++) acc[mt][nt][e] = 0.f;

    const int NCH = K / BK;

#define ISSUE_CHUNK(c, s) do {                                                \
        uint32_t a_dst = smem_base + (uint32_t)((s) * GS_STAGE) * 4;          \
        uint32_t b_dst = a_dst + CH_WORDS * 4;                                \
        _Pragma("unroll")                                                     \
        for (int i = 0; i < 4; i++) {                                         \
            CP_ASYNC16(a_dst + goff[i], a_src[i] + (c) * BK);                 \
            CP_ASYNC16(b_dst + goff[i], b_src[i] + (c) * BK);                 \
        }                                                                     \
    } while (0)

#define COMPUTE_CHUNK(s) do {                                                 \
        const uint32_t* Asb = sm + (s) * GS_STAGE;                            \
        const uint32_t* Bsb = Asb + CH_WORDS;                                 \
        _Pragma("unroll")                                                     \
        for (int ks = 0; ks < 4; ks++) {                                      \
            int o0 = (((2 * ks) ^ q) << 2) + r;                               \
            int o1 = (((2 * ks + 1) ^ q) << 2) + r;                           \
            uint32_t af[4][4];                                                \
            _Pragma("unroll")                                                 \
            for (int mt = 0; mt < 4; mt++) {                                  \
                int base = (wm * 64 + mt * 16 + q) * 32;                      \
                af[mt][0] = Asb[base + o0];                                   \
                af[mt][1] = Asb[base + 256 + o0];                             \
                af[mt][2] = Asb[base + o1];                                   \
                af[mt][3] = Asb[base + 256 + o1];                             \
            }                                                                 \
            uint32_t bf[4][2];                                                \
            _Pragma("unroll")                                                 \
            for (int nt = 0; nt < 4; nt++) {                                  \
                int base = (wn * 32 + nt * 8 + q) * 32;                       \
                bf[nt][0] = Bsb[base + o0];                                   \
                bf[nt][1] = Bsb[base + o1];                                   \
            }                                                                 \
            _Pragma("unroll")                                                 \
            for (int mt = 0; mt < 4; mt++)                                    \
                _Pragma("unroll")                                             \
                for (int nt = 0; nt < 4; nt++)                                \
                    mma_tf32(acc[mt][nt], af[mt], bf[nt]);                    \
        }                                                                     \
    } while (0)

    ISSUE_CHUNK(0, 0); CP_COMMIT();
    ISSUE_CHUNK(1, 1); CP_COMMIT();

    int sc = 0;
    for (int c = 0; c < NCH; c++) {
        CP_WAIT1();
        __syncthreads();
        COMPUTE_CHUNK(sc);
        if (c + 2 < NCH) {
            int ns = sc + 2; if (ns >= GS_NSTAGE) ns -= GS_NSTAGE;
            ISSUE_CHUNK(c + 2, ns);
        }
        CP_COMMIT();
        sc = (sc + 1 == GS_NSTAGE) ? 0 : sc + 1;
    }

#pragma unroll
    for (int nt = 0; nt < 4; nt++) {
        int col = n0 + wn * 32 + nt * 8 + 2 * r;
        float2 bv = *(const float2*)&bias[col];
#pragma unroll
        for (int mt = 0; mt < 4; mt++) {
            int row = m0 + wm * 64 + mt * 16 + q;
            float2 o0 = make_float2(acc[mt][nt][0] + bv.x, acc[mt][nt][1] + bv.y);
            float2 o1 = make_float2(acc[mt][nt][2] + bv.x, acc[mt][nt][3] + bv.y);
            if (round_c) {
                o0.x = f2tf32f(o0.x); o0.y = f2tf32f(o0.y);
                o1.x = f2tf32f(o1.x); o1.y = f2tf32f(o1.y);
            }
            *(float2*)(C + (size_t)row * N + col)       = o0;
            *(float2*)(C + (size_t)(row + 8) * N + col) = o1;
        }
    }
#undef ISSUE_CHUNK
#undef COMPUTE_CHUNK
}

// ===========================================================================
// Attention V^T layout (pair-swizzled, validated):
// row stride 34 words; pair (k, k+4) at f2-index f = 4*(k>>3) + (k&3),
// word o = (k&7)>>2; f XOR'd with (row&3)<<2.
// ===========================================================================
#define TILE_W 34
__device__ __forceinline__ int sw_off(int row, int f, int o) {
    return row * TILE_W + 2 * (f ^ ((row & 3) << 2)) + o;
}

// ===========================================================================
// Flash attention, tf32 mma.sync + cp.async.
// 256 threads (8 warps); block = 128 queries of one (b,h); key tiles of 64.
// Q (and later P) in 2 chunk-layout buffers (128x32 each); K triple-buffered
// chunk-layout (64x32 x2 per stage) via cp.async; V^T pair-layout via LDG+STS.
// Inputs (proj) are already tf32-rounded -> HW truncation in mma is lossless.
// ===========================================================================
#define AQ_CH 4096                     // words per Q/P chunk (128x32)
#define AK_CH 2048                     // words per K chunk (64x32)
#define A_QC  0                        // 2 chunks  -> 8192 words
#define A_KC  8192                     // 3 stages x 4096 -> 12288 words
#define A_VT  20480                    // 2 x 2176 -> 4352 words
#define A_MSK 24832                    // 64 words
#define ATTN_SMEM_WORDS (24832 + 64)   // 99584 B

__global__ void __launch_bounds__(256, 2)
attn_mma(const float* __restrict__ proj, const uint32_t* __restrict__ mask,
         float* __restrict__ out)
{
    extern __shared__ uint32_t sm[];
    const uint32_t smb = smem_u32(sm);
    uint32_t* QC = sm + A_QC;
    uint32_t* VT[2] = { sm + A_VT, sm + A_VT + 2176 };
    float* msk = (float*)(sm + A_MSK);

    const int tid  = threadIdx.x;
    const int w    = tid >> 5;
    const int lane = tid & 31;
    const int q = lane >> 2;
    const int r = lane & 3;
    const int h = blockIdx.y, b = blockIdx.z;
    const int q0 = blockIdx.x * 128;
    const int NT = TSEQ / 64;

    // K-issue helper
#define ISSUE_K(kt_, st_) do {                                                \
        int s0_ = (kt_) * 64;                                                 \
        _Pragma("unroll")                                                     \
        for (int i = 0; i < 4; i++) {                                         \
            int f4 = i * 256 + tid;                                           \
            int row = f4 >> 4, g = f4 & 15;                                   \
            const float* src = proj +                                         \
                ((size_t)(s0_ + row) * BB + b) * E3 + EMB + h * HD + g * 4;   \
            uint32_t dst = smb + (uint32_t)(A_KC + (st_) * 4096 +             \
                (g >> 3) * AK_CH + row * 32 + (((g & 7) ^ (row & 7)) << 2)) * 4; \
            CP_ASYNC16(dst, src);                                             \
        }                                                                     \
    } while (0)

    // ---- prologue: Q + K(0) | K(1) ----
#pragma unroll
    for (int i = 0; i < 8; i++) {
        int f4 = i * 256 + tid;
        int row = f4 >> 4, g = f4 & 15;
        const float* src = proj + ((size_t)(q0 + row) * BB + b) * E3 + h * HD + g * 4;
        uint32_t dst = smb + (uint32_t)(A_QC + (g >> 3) * AQ_CH +
            row * 32 + (((g & 7) ^ (row & 7)) << 2)) * 4;
        CP_ASYNC16(dst, src);
    }
    ISSUE_K(0, 0);
    CP_COMMIT();
    ISSUE_K(1, 1);
    CP_COMMIT();
    CP_WAIT1();                 // Q + K(0) landed
    __syncthreads();

    // ---- preload Q fragments (QC dead afterwards -> reused for P) ----
    uint32_t afq[8][4];
#pragma unroll
    for (int kg = 0; kg < 8; kg++) {
        int ks = kg & 3;
        int o0 = (((2 * ks) ^ q) << 2) + r;
        int o1 = (((2 * ks + 1) ^ q) << 2) + r;
        const uint32_t* base = QC + (kg >> 2) * AQ_CH + (w * 16 + q) * 32;
        afq[kg][0] = base[o0];
        afq[kg][1] = base[256 + o0];
        afq[kg][2] = base[o1];
        afq[kg][3] = base[256 + o1];
    }

    float oacc[8][4];
#pragma unroll
    for (int dt = 0; dt < 8; dt++)
#pragma unroll
        for (int e = 0; e < 4; e++) oacc[dt][e] = 0.f;
    float m0 = -1e30f, m1 = -1e30f, l0 = 0.f, l1 = 0.f;

    const uint32_t* mrow = mask + (size_t)b * TSEQ;

    for (int kt = 0; kt < NT; kt++) {
        const int s0 = kt * 64;
        const int st = kt % 3;

        // ---- V LDG early (overlaps K wait) ----
        float4 vreg[4];
#pragma unroll
        for (int i = 0; i < 4; i++) {
            int f4 = i * 256 + tid;
            int srow = f4 >> 4, g = f4 & 15;
            vreg[i] = *(const float4*)(proj +
                ((size_t)(s0 + srow) * BB + b) * E3 + 2 * EMB + h * HD + g * 4);
        }

        CP_WAIT1();                  // K(kt) landed; K(kt+1) pending
        __syncthreads();             // prev tile's VT/P readers done; K visible

        if (kt + 2 < NT) {
            int ns = st + 2; if (ns >= 3) ns -= 3;
            ISSUE_K(kt + 2, ns);
        }
        CP_COMMIT();

        // ---- V^T scatter store (values already tf32; no cvt) ----
#pragma unroll
        for (int i = 0; i < 4; i++) {
            int f4 = i * 256 + tid;
            int srow = f4 >> 4, g = f4 & 15;
            int kl = srow & 31;
            int f = 4 * (kl >> 3) + (kl & 3);
            int o = (kl & 7) >> 2;
            uint32_t* vb = VT[srow >> 5];
            const float* vv = (const float*)&vreg[i];
#pragma unroll
            for (int j = 0; j < 4; j++)
                vb[sw_off(g * 4 + j, f, o)] = __float_as_uint(vv[j]);
        }
        if (tid < 64)
            msk[tid] = (mrow[s0 + tid] != 0u) ? -1e30f : 0.f;
        int nvalid = __syncthreads_count((int)(mrow[s0 + (tid & 63)] == 0u));
        if (nvalid == 0) break;      // monotone pad suffix

        // ---- S = Q K^T ----
        float sacc[8][4];
#pragma unroll
        for (int nt = 0; nt < 8; nt++)
#pragma unroll
            for (int e = 0; e < 4; e++) sacc[nt][e] = 0.f;
        const uint32_t* Kst = sm + A_KC + st * 4096;
#pragma unroll
        for (int kg = 0; kg < 8; kg++) {
            int ks = kg & 3;
            int o0 = (((2 * ks) ^ q) << 2) + r;
            int o1 = (((2 * ks + 1) ^ q) << 2) + r;
            const uint32_t* kb = Kst + (kg >> 2) * AK_CH;
#pragma unroll
            for (int nt = 0; nt < 8; nt++) {
                int base = (nt * 8 + q) * 32;
                uint32_t bf[2] = { kb[base + o0], kb[base + o1] };
                mma_tf32(sacc[nt], afq[kg], bf);
            }
        }

        // ---- scale (folded 0.125) + mask + online softmax ----
        float mx0 = -1e30f, mx1 = -1e30f;
#pragma unroll
        for (int nt = 0; nt < 8; nt++) {
            float mk0 = msk[nt * 8 + 2 * r];
            float mk1 = msk[nt * 8 + 2 * r + 1];
            sacc[nt][0] = fmaf(sacc[nt][0], SCALING, mk0);
            sacc[nt][1] = fmaf(sacc[nt][1], SCALING, mk1);
            sacc[nt][2] = fmaf(sacc[nt][2], SCALING, mk0);
            sacc[nt][3] = fmaf(sacc[nt][3], SCALING, mk1);
            mx0 = fmaxf(mx0, fmaxf(sacc[nt][0], sacc[nt][1]));
            mx1 = fmaxf(mx1, fmaxf(sacc[nt][2], sacc[nt][3]));
        }
        mx0 = fmaxf(mx0, __shfl_xor_sync(0xffffffffu, mx0, 1));
        mx0 = fmaxf(mx0, __shfl_xor_sync(0xffffffffu, mx0, 2));
        mx1 = fmaxf(mx1, __shfl_xor_sync(0xffffffffu, mx1, 1));
        mx1 = fmaxf(mx1, __shfl_xor_sync(0xffffffffu, mx1, 2));

        float mn0 = fmaxf(m0, mx0), mn1 = fmaxf(m1, mx1);
        float c0 = fast_exp(m0 - mn0), c1 = fast_exp(m1 - mn1);
        m0 = mn0; m1 = mn1;

        float sum0 = 0.f, sum1 = 0.f;
#pragma unroll
        for (int nt = 0; nt < 8; nt++) {
            sacc[nt][0] = fast_exp(sacc[nt][0] - mn0);
            sacc[nt][1] = fast_exp(sacc[nt][1] - mn0);
            sacc[nt][2] = fast_exp(sacc[nt][2] - mn1);
            sacc[nt][3] = fast_exp(sacc[nt][3] - mn1);
            sum0 += sacc[nt][0] + sacc[nt][1];
            sum1 += sacc[nt][2] + sacc[nt][3];
        }
        sum0 += __shfl_xor_sync(0xffffffffu, sum0, 1);
        sum0 += __shfl_xor_sync(0xffffffffu, sum0, 2);
        sum1 += __shfl_xor_sync(0xffffffffu, sum1, 1);
        sum1 += __shfl_xor_sync(0xffffffffu, sum1, 2);

        l0 = l0 * c0 + sum0;
        l1 = l1 * c1 + sum1;
#pragma unroll
        for (int dt = 0; dt < 8; dt++) {
            oacc[dt][0] *= c0; oacc[dt][1] *= c0;
            oacc[dt][2] *= c1; oacc[dt][3] *= c1;
        }

        // ---- store P fragments into QC chunks (STS.64 pairs) ----
        {
            int row0 = w * 16 + q;
            int row1 = row0 + 8;
            int kA = 2 * r;                      // k3 in {0,2}; pair is contiguous
            int k4base = r >> 1;
#pragma unroll
            for (int nt = 0; nt < 8; nt++) {
                uint32_t* pc = QC + (nt >> 2) * AQ_CH;
                int k4 = (nt & 3) * 2 + k4base;
                int w0 = row0 * 32 + ((k4 ^ q) << 2) + (kA & 3);
                int w1 = row1 * 32 + ((k4 ^ q) << 2) + (kA & 3);
                *(uint2*)&pc[w0] = make_uint2(f2tf32(sacc[nt][0]), f2tf32(sacc[nt][1]));
                *(uint2*)&pc[w1] = make_uint2(f2tf32(sacc[nt][2]), f2tf32(sacc[nt][3]));
            }
        }
        __syncwarp();                // P rows are warp-private

        // ---- O += P V ----
#pragma unroll
        for (int kg = 0; kg < 8; kg++) {
            int ks = kg & 3;
            int o0 = (((2 * ks) ^ q) << 2) + r;
            int o1 = (((2 * ks + 1) ^ q) << 2) + r;
            const uint32_t* pbase = QC + (kg >> 2) * AQ_CH + (w * 16 + q) * 32;
            uint32_t afp[4] = { pbase[o0], pbase[256 + o0],
                                pbase[o1], pbase[256 + o1] };
            int fidx = 4 * (kg & 3) + r;
            const uint32_t* vb2 = VT[kg >> 2];
#pragma unroll
            for (int dt = 0; dt < 8; dt++) {
                uint2 b2 = *(const uint2*)&vb2[sw_off(dt * 8 + q, fidx, 0)];
                uint32_t bfv[2] = { b2.x, b2.y };
                mma_tf32(oacc[dt], afp, bfv);
            }
        }
    }
    CP_WAIT0();                      // drain any pending prefetch

    // ---- epilogue: normalize, round to tf32 (feeds GEMM2), write ----
    float inv0 = 1.0f / l0, inv1 = 1.0f / l1;
    int row0 = q0 + w * 16 + q;
#pragma unroll
    for (int dt = 0; dt < 8; dt++) {
        int col = h * HD + dt * 8 + 2 * r;
        float2 o0 = make_float2(f2tf32f(oacc[dt][0] * inv0), f2tf32f(oacc[dt][1] * inv0));
        float2 o1 = make_float2(f2tf32f(oacc[dt][2] * inv1), f2tf32f(oacc[dt][3] * inv1));
        *(float2*)(out + ((size_t)row0 * BB + b) * EMB + col)       = o0;
        *(float2*)(out + ((size_t)(row0 + 8) * BB + b) * EMB + col) = o1;
    }
#undef ISSUE_K
}

// ---------------------------------------------------------------------------
extern "C" void kernel_launch(void* const* d_in, const int* in_sizes, int n_in,
                              void* d_out, int out_size)
{
    const float*    query = (const float*)d_in[0];          // [T,B,E]
    const uint32_t* mask  = (const uint32_t*)d_in[1];       // [B,T] bool widened to 4B
    const float*    W_in  = (const float*)d_in[2];          // [3E,E]
    const float*    b_in  = (const float*)d_in[3];          // [3E]
    const float*    W_out = (const float*)d_in[4];          // [E,E]
    const float*    b_out = (const float*)d_in[5];          // [E]
    float*          out   = (float*)d_out;                  // [T,B,E]

    float *proj, *attn, *qr, *winr, *woutr;
    cudaGetSymbolAddress((void**)&proj,  g_proj);
    cudaGetSymbolAddress((void**)&attn,  g_attn);
    cudaGetSymbolAddress((void**)&qr,    g_qr);
    cudaGetSymbolAddress((void**)&winr,  g_winr);
    cudaGetSymbolAddress((void**)&woutr, g_woutr);

    const int gemm_smem = GS_NSTAGE * GS_STAGE * 4;         // 98304 B
    cudaFuncSetAttribute(mma_gemm_nt_bias,
                         cudaFuncAttributeMaxDynamicSharedMemorySize, gemm_smem);
    const int attn_smem = ATTN_SMEM_WORDS * 4;              // 99584 B
    cudaFuncSetAttribute(attn_mma,
                         cudaFuncAttributeMaxDynamicSharedMemorySize, attn_smem);

    // 0) pre-round operands to tf32 (makes cp.async + HW-truncation lossless)
    {
        int n4q = MROWS * EMB / 4;
        round_tf32_kernel<<<(n4q + 255) / 256, 256>>>(query, qr, n4q);
        int n4w = E3 * EMB / 4;
        round_tf32_kernel<<<(n4w + 255) / 256, 256>>>(W_in, winr, n4w);
        int n4o = EMB * EMB / 4;
        round_tf32_kernel<<<(n4o + 255) / 256, 256>>>(W_out, woutr, n4o);
    }

    // 1) QKV projection: [4096,3072] = qr @ winr^T + b_in  (round proj to tf32)
    mma_gemm_nt_bias<<<dim3(E3 / 128, MROWS / 128), 256, gemm_smem>>>(
        qr, winr, b_in, proj, MROWS, E3, EMB, 1);

    // 2) flash attention (tf32 mma.sync + cp.async), 128-query blocks per (b,h)
    attn_mma<<<dim3(TSEQ / 128, NH, BB), 256, attn_smem>>>(proj, mask, attn);

    // 3) output projection: [4096,1024] = attn @ woutr^T + b_out (no rounding)
    mma_gemm_nt_bias<<<dim3(EMB / 128, MROWS / 128), 256, gemm_smem>>>(
        attn, woutr, b_out, out, MROWS, EMB, EMB, 0);
}